// round 1
// baseline (speedup 1.0000x reference)
#include <cuda_runtime.h>

// ============================================================================
// MeToken: z_q = softmax(topk_gated(x @ cb^T) / 0.01) @ cb
//
// Key identity: non-topk gated scores are 0 (not -inf), so with
//   m = max(top1, 0), w_k = exp((s_k - m)/tau), b = exp(-m/tau):
//   Z   = w0+w1+w2 + (C-K)*b
//   z_q = (w0*cb0 + w1*cb1 + w2*cb2 + b*(colsum(cb) - cb0 - cb1 - cb2)) / Z
// => only the scores GEMM + top-3 is expensive. Done in exact fp32 via
//    packed fma.rn.f32x2 (2x fp32 rate on sm_103a).
// ============================================================================

#define N_ROWS 8192
#define DIM 128
#define N_CODES 16384
#define TOPK 3

#define M_TILE 128
#define ROW_BLOCKS (N_ROWS / M_TILE)            // 64
#define CB_SPLITS 16
#define CODES_PER_SPLIT (N_CODES / CB_SPLITS)   // 1024
#define CHUNK 128
#define CHUNKS_PER_SPLIT (CODES_PER_SPLIT / CHUNK)  // 8
#define PAD 132                                  // floats per shared row (16B aligned, conflict-friendly)
#define SMEM_BYTES (2 * 128 * PAD * 4)           // 135168 B

// Scratch (no allocs allowed -> __device__ globals)
__device__ float g_part_cbsum[128 * DIM];
__device__ float g_cbsum[DIM];
__device__ float g_pval[N_ROWS * CB_SPLITS * TOPK];
__device__ int   g_pidx[N_ROWS * CB_SPLITS * TOPK];

typedef unsigned long long ull;

__device__ __forceinline__ ull pack2(float lo, float hi) {
    ull r;
    asm("mov.b64 %0, {%1, %2};" : "=l"(r) : "f"(lo), "f"(hi));
    return r;
}
__device__ __forceinline__ void unpack2(ull v, float& lo, float& hi) {
    asm("mov.b64 {%0, %1}, %2;" : "=f"(lo), "=f"(hi) : "l"(v));
}
// Packed dual-fp32 FMA (Blackwell FFMA2) — only reachable via PTX.
__device__ __forceinline__ void ffma2(ull& d, ull a, ull b) {
    asm("fma.rn.f32x2 %0, %1, %2, %0;" : "+l"(d) : "l"(a), "l"(b));
}
__device__ __forceinline__ float f4c(const float4 v, int q) {
    return q == 0 ? v.x : q == 1 ? v.y : q == 2 ? v.z : v.w;
}
__device__ __forceinline__ void ins3(float s, int c, float v[3], int ix[3]) {
    if (s > v[2]) {
        if (s > v[1]) {
            v[2] = v[1]; ix[2] = ix[1];
            if (s > v[0]) { v[1] = v[0]; ix[1] = ix[0]; v[0] = s; ix[0] = c; }
            else          { v[1] = s;    ix[1] = c; }
        } else { v[2] = s; ix[2] = c; }
    }
}

// ---------------------------------------------------------------------------
// Codebook column sums (two deterministic stages, no float atomics)
// ---------------------------------------------------------------------------
__global__ void cbsum_part_kernel(const float* __restrict__ cb) {
    const int b = blockIdx.x;      // 128 blocks x 128 codes
    const int d = threadIdx.x;     // 128 threads = one column each
    const float* p = cb + (size_t)b * 128 * DIM + d;
    float s = 0.0f;
#pragma unroll 8
    for (int c = 0; c < 128; ++c) s += p[(size_t)c * DIM];
    g_part_cbsum[b * DIM + d] = s;
}
__global__ void cbsum_comb_kernel() {
    const int d = threadIdx.x;
    float s = 0.0f;
#pragma unroll 8
    for (int b = 0; b < 128; ++b) s += g_part_cbsum[b * DIM + d];
    g_cbsum[d] = s;
}

// ---------------------------------------------------------------------------
// Main: fp32 scores GEMM (FFMA2) fused with per-row top-3 (partial per split)
// Grid (64 row-blocks, 16 codebook splits), 256 threads.
// Thread tile: 8 rows x 8 codes  =  4 row-pairs (f32x2 lanes) x 8 codes.
// ---------------------------------------------------------------------------
__global__ void __launch_bounds__(256, 1)
score_topk_kernel(const float* __restrict__ x, const float* __restrict__ cb) {
    extern __shared__ float sm[];
    float* shx = sm;                    // [128 rows][PAD]
    float* shc = sm + M_TILE * PAD;     // [128 codes][PAD]

    const int tid = threadIdx.x;
    const int tx = tid & 15;            // code group
    const int ty = tid >> 4;            // row group
    const int row0  = blockIdx.x * M_TILE;
    const int code0 = blockIdx.y * CODES_PER_SPLIT;

    // Load x block (coalesced gmem, float4 STS)
    for (int idx = tid; idx < M_TILE * (DIM / 4); idx += 256) {
        const int r = idx >> 5, d4 = idx & 31;
        *(float4*)(shx + r * PAD + d4 * 4) =
            *(const float4*)(x + (size_t)(row0 + r) * DIM + d4 * 4);
    }

    float tv[8][3];
    int   tix[8][3];
#pragma unroll
    for (int i = 0; i < 8; ++i)
#pragma unroll
        for (int s = 0; s < 3; ++s) { tv[i][s] = -3.0e38f; tix[i][s] = 0; }

    for (int ch = 0; ch < CHUNKS_PER_SPLIT; ++ch) {
        __syncthreads();   // protect shc reuse (also covers shx store on iter 0)
        const int cbase = code0 + ch * CHUNK;
        for (int idx = tid; idx < CHUNK * (DIM / 4); idx += 256) {
            const int c = idx >> 5, d4 = idx & 31;
            *(float4*)(shc + c * PAD + d4 * 4) =
                *(const float4*)(cb + (size_t)(cbase + c) * DIM + d4 * 4);
        }
        __syncthreads();

        ull acc[4][8];
#pragma unroll
        for (int p = 0; p < 4; ++p)
#pragma unroll
            for (int j = 0; j < 8; ++j) acc[p][j] = 0ull;

        const float* xb  = shx + (ty * 8) * PAD;
        const float* cbb = shc + tx * PAD;

#pragma unroll 1
        for (int k4 = 0; k4 < DIM / 4; ++k4) {
            float4 A[8], B[8];
#pragma unroll
            for (int i = 0; i < 8; ++i)
                A[i] = *(const float4*)(xb + i * PAD + k4 * 4);      // broadcast across tx
#pragma unroll
            for (int j = 0; j < 8; ++j)
                B[j] = *(const float4*)(cbb + j * 16 * PAD + k4 * 4); // codes tx + 16j
#pragma unroll
            for (int q = 0; q < 4; ++q) {
                ull ap[4], bd[8];
#pragma unroll
                for (int p = 0; p < 4; ++p)
                    ap[p] = pack2(f4c(A[2 * p], q), f4c(A[2 * p + 1], q));
#pragma unroll
                for (int j = 0; j < 8; ++j) { const float b = f4c(B[j], q); bd[j] = pack2(b, b); }
#pragma unroll
                for (int p = 0; p < 4; ++p)
#pragma unroll
                    for (int j = 0; j < 8; ++j) ffma2(acc[p][j], ap[p], bd[j]);
            }
        }

        // Fold this chunk's 64 scores into per-(thread,row) top-3
#pragma unroll
        for (int p = 0; p < 4; ++p)
#pragma unroll
            for (int j = 0; j < 8; ++j) {
                float lo, hi;
                unpack2(acc[p][j], lo, hi);
                const int code = cbase + tx + 16 * j;
                ins3(lo, code, tv[2 * p],     tix[2 * p]);
                ins3(hi, code, tv[2 * p + 1], tix[2 * p + 1]);
            }
    }

    // CTA-level merge: 16 threads per row, 48 candidates -> top-3
    __syncthreads();
    float* rv = shc;                       // reuse: 128*48 floats
    int*   ri = (int*)(shc + M_TILE * 48); // + 128*48 ints (fits in 67.5KB)
#pragma unroll
    for (int i = 0; i < 8; ++i) {
        const int r = ty * 8 + i;
#pragma unroll
        for (int s = 0; s < 3; ++s) {
            rv[r * 48 + tx * 3 + s] = tv[i][s];
            ri[r * 48 + tx * 3 + s] = tix[i][s];
        }
    }
    __syncthreads();
    if (tid < M_TILE) {
        const int r = tid;
        float v[3] = { -3.0e38f, -3.0e38f, -3.0e38f };
        int ix[3] = { 0, 0, 0 };
#pragma unroll 1
        for (int q = 0; q < 48; ++q) ins3(rv[r * 48 + q], ri[r * 48 + q], v, ix);
        const int grow = row0 + r;
        const int base = grow * (CB_SPLITS * TOPK) + blockIdx.y * TOPK;
#pragma unroll
        for (int s = 0; s < 3; ++s) { g_pval[base + s] = v[s]; g_pidx[base + s] = ix[s]; }
    }
}

// ---------------------------------------------------------------------------
// Finalize: merge 16 partial top-3s, softmax identity, emit z_q row
// ---------------------------------------------------------------------------
__global__ void finalize_kernel(const float* __restrict__ cb, float* __restrict__ out) {
    const int row = blockIdx.x;
    __shared__ float sv[CB_SPLITS * TOPK];
    __shared__ int   si[CB_SPLITS * TOPK];
    const int tid = threadIdx.x;   // 128 = DIM
    if (tid < CB_SPLITS * TOPK) {
        sv[tid] = g_pval[row * (CB_SPLITS * TOPK) + tid];
        si[tid] = g_pidx[row * (CB_SPLITS * TOPK) + tid];
    }
    __syncthreads();

    float v[3] = { -3.0e38f, -3.0e38f, -3.0e38f };
    int ix[3] = { 0, 0, 0 };
#pragma unroll 1
    for (int q = 0; q < CB_SPLITS * TOPK; ++q) ins3(sv[q], si[q], v, ix);

    const float INV_TAU = 1.0f / 0.01f;
    const float m  = fmaxf(v[0], 0.0f);
    const float w0 = expf((v[0] - m) * INV_TAU);
    const float w1 = expf((v[1] - m) * INV_TAU);
    const float w2 = expf((v[2] - m) * INV_TAU);
    const float b  = expf(-m * INV_TAU);     // weight of every non-topk entry
    const float Z  = w0 + w1 + w2 + b * (float)(N_CODES - TOPK);
    const float invZ = 1.0f / Z;

    const int d = tid;
    const float c0 = cb[(size_t)ix[0] * DIM + d];
    const float c1 = cb[(size_t)ix[1] * DIM + d];
    const float c2 = cb[(size_t)ix[2] * DIM + d];
    const float cs = g_cbsum[d];
    out[(size_t)row * DIM + d] =
        (w0 * c0 + w1 * c1 + w2 * c2 + b * (cs - c0 - c1 - c2)) * invZ;
}

// ---------------------------------------------------------------------------
extern "C" void kernel_launch(void* const* d_in, const int* in_sizes, int n_in,
                              void* d_out, int out_size) {
    const float* x  = (const float*)d_in[0];
    const float* cb = (const float*)d_in[1];
    // Defensive: identify tensors by size (x: 8192*128, cb: 16384*128)
    if (n_in >= 2 && in_sizes[0] == N_CODES * DIM && in_sizes[1] == N_ROWS * DIM) {
        x  = (const float*)d_in[1];
        cb = (const float*)d_in[0];
    }
    float* out = (float*)d_out;

    cudaFuncSetAttribute(score_topk_kernel,
                         cudaFuncAttributeMaxDynamicSharedMemorySize, SMEM_BYTES);

    cbsum_part_kernel<<<128, 128>>>(cb);
    cbsum_comb_kernel<<<1, 128>>>();
    score_topk_kernel<<<dim3(ROW_BLOCKS, CB_SPLITS), 256, SMEM_BYTES>>>(x, cb);
    finalize_kernel<<<N_ROWS, DIM>>>(cb, out);
}

// round 4
// speedup vs baseline: 2.5762x; 2.5762x over previous
#include <cuda_runtime.h>
#include <cuda_bf16.h>
#include <cstdint>

// ============================================================================
// MeToken: z_q = softmax(topk3_gated(x @ cb^T) / 0.01) @ cb
//
// Identity (non-topk gated scores are 0, not -inf):
//   m = max(top1, 0), w_k = exp((s_k-m)/tau), b = exp(-m/tau)
//   Z   = w0+w1+w2 + (C-K)*b
//   z_q = (w0*cb0 + w1*cb1 + w2*cb2 + b*(colsum(cb) - cb0-cb1-cb2)) / Z
//
// Pipeline (tcgen05 rejected by ptxas target sm_103 -> use mma.sync HMMA):
//   1) convert x, cb -> bf16 (screening precision; cb convert fused w/ colsum)
//   2) mma.sync bf16 GEMM, CTA 128x128, fused per-row top-8 per N-tile
//   3) finalize: merge 128x8 candidates, EXACT fp32 rescore of top-8 pool,
//      top-3 + softmax identity -> z_q
// ============================================================================

#define N_ROWS 8192
#define DIM 128
#define N_CODES 16384
#define TOPK 3

#define MT 128
#define NT 128
#define NTILES (N_CODES / NT)          // 128
#define MTILES (N_ROWS / MT)           // 64
#define CAND 8
#define STRIDE 136                      // bf16 per smem row (272B, 68 words)
#define TILE_SMEM_BYTES (2 * 128 * STRIDE * 2)   // 69632

// ---------------- scratch (no allocs allowed) ----------------
__device__ __nv_bfloat16 g_xb[N_ROWS * DIM];
__device__ __nv_bfloat16 g_cbb[N_CODES * DIM];
__device__ float g_part_cbsum[128 * DIM];
__device__ float g_cbsum[DIM];
__device__ float g_cval[(size_t)N_ROWS * NTILES * CAND];
__device__ int   g_cidx[(size_t)N_ROWS * NTILES * CAND];

// ---------------- helpers ----------------
__device__ __forceinline__ uint32_t smem_u32(const void* p) {
    uint32_t a;
    asm("{ .reg .u64 t; cvta.to.shared.u64 t, %1; cvt.u32.u64 %0, t; }" : "=r"(a) : "l"(p));
    return a;
}
__device__ __forceinline__ uint32_t lds32(uint32_t addr) {
    uint32_t v;
    asm volatile("ld.shared.b32 %0, [%1];" : "=r"(v) : "r"(addr));
    return v;
}
__device__ __forceinline__ void sts128(uint32_t addr, uint4 v) {
    asm volatile("st.shared.v4.b32 [%0], {%1,%2,%3,%4};"
                 :: "r"(addr), "r"(v.x), "r"(v.y), "r"(v.z), "r"(v.w) : "memory");
}
__device__ __forceinline__ void mma16816(float c[4], const uint32_t a[4], const uint32_t b[2]) {
    asm volatile(
        "mma.sync.aligned.m16n8k16.row.col.f32.bf16.bf16.f32 "
        "{%0,%1,%2,%3}, {%4,%5,%6,%7}, {%8,%9}, {%0,%1,%2,%3};"
        : "+f"(c[0]), "+f"(c[1]), "+f"(c[2]), "+f"(c[3])
        : "r"(a[0]), "r"(a[1]), "r"(a[2]), "r"(a[3]), "r"(b[0]), "r"(b[1]));
}
__device__ __forceinline__ void ins8(float s, int c, float v[8], int ix[8]) {
    if (s <= v[7]) return;
    v[7] = s; ix[7] = c;
#pragma unroll
    for (int t = 7; t > 0; --t) {
        if (v[t] > v[t - 1]) {
            float tv = v[t]; v[t] = v[t - 1]; v[t - 1] = tv;
            int ti = ix[t]; ix[t] = ix[t - 1]; ix[t - 1] = ti;
        }
    }
}
__device__ __forceinline__ void ins3(float s, int c, float v[3], int ix[3]) {
    if (s > v[2]) {
        if (s > v[1]) {
            v[2] = v[1]; ix[2] = ix[1];
            if (s > v[0]) { v[1] = v[0]; ix[1] = ix[0]; v[0] = s; ix[0] = c; }
            else          { v[1] = s;    ix[1] = c; }
        } else { v[2] = s; ix[2] = c; }
    }
}

// ---------------------------------------------------------------------------
// 1) converts + column sums
// ---------------------------------------------------------------------------
__global__ void convert_x_kernel(const float* __restrict__ x) {
    const int i = (blockIdx.x * 256 + threadIdx.x) * 4;
    const float4 v = *(const float4*)(x + i);
    __nv_bfloat162* o = (__nv_bfloat162*)(g_xb + i);
    o[0] = __nv_bfloat162(__float2bfloat16_rn(v.x), __float2bfloat16_rn(v.y));
    o[1] = __nv_bfloat162(__float2bfloat16_rn(v.z), __float2bfloat16_rn(v.w));
}
__global__ void convert_cb_kernel(const float* __restrict__ cb) {
    const int b = blockIdx.x;   // 128 blocks x 128 codes each
    const int d = threadIdx.x;  // column
    const float* p = cb + (size_t)b * 128 * DIM + d;
    __nv_bfloat16* q = g_cbb + (size_t)b * 128 * DIM + d;
    float s = 0.0f;
#pragma unroll 8
    for (int c = 0; c < 128; ++c) {
        const float v = p[(size_t)c * DIM];
        s += v;
        q[(size_t)c * DIM] = __float2bfloat16_rn(v);
    }
    g_part_cbsum[b * DIM + d] = s;
}
__global__ void cbsum_comb_kernel() {
    const int d = threadIdx.x;
    float s = 0.0f;
#pragma unroll 8
    for (int b = 0; b < 128; ++b) s += g_part_cbsum[b * DIM + d];
    g_cbsum[d] = s;
}

// ---------------------------------------------------------------------------
// 2) mma.sync bf16 GEMM (CTA 128x128, K=128) + fused per-row top-8
//    8 warps = 2(M) x 4(N); warp tile 64x32 = 4 mfrag x 4 nfrag m16n8k16
// ---------------------------------------------------------------------------
__global__ void __launch_bounds__(256, 2)
gemm_topk_kernel(const __nv_bfloat16* __restrict__ xb,
                 const __nv_bfloat16* __restrict__ cbb) {
    extern __shared__ __align__(16) char smem[];
    const uint32_t sbase = smem_u32(smem);
    const uint32_t sA = sbase;
    const uint32_t sB = sbase + 128 * STRIDE * 2;

    const int tid = threadIdx.x;
    const int wid = tid >> 5, lane = tid & 31;
    const int g = lane >> 2, tig = lane & 3;
    const int wm = wid & 1, wn = wid >> 1;

    const int row0  = blockIdx.x * MT;
    const int code0 = blockIdx.y * NT;

    // ---- fill tiles: 128 rows x 16 uint4 each, padded stride ----
    {
        const uint4* gx = (const uint4*)(xb + (size_t)row0 * DIM);
        const uint4* gc = (const uint4*)(cbb + (size_t)code0 * DIM);
#pragma unroll
        for (int i = tid; i < 128 * 16; i += 256) {
            const int r = i >> 4, kc = i & 15;
            sts128(sA + r * (STRIDE * 2) + kc * 16, gx[r * 16 + kc]);
        }
#pragma unroll
        for (int i = tid; i < 128 * 16; i += 256) {
            const int r = i >> 4, kc = i & 15;
            sts128(sB + r * (STRIDE * 2) + kc * 16, gc[r * 16 + kc]);
        }
    }
    __syncthreads();

    float acc[4][4][4];
#pragma unroll
    for (int i = 0; i < 4; ++i)
#pragma unroll
        for (int j = 0; j < 4; ++j)
#pragma unroll
            for (int c = 0; c < 4; ++c) acc[i][j][c] = 0.0f;

    // byte base addresses of each lane's fragment elements
    const uint32_t aBase = sA + (uint32_t)(wm * 64 + g) * (STRIDE * 2) + tig * 4;
    const uint32_t bBase = sB + (uint32_t)(wn * 32 + g) * (STRIDE * 2) + tig * 4;

#pragma unroll
    for (int ks = 0; ks < 8; ++ks) {
        const uint32_t kOff = ks * 32;   // 16 bf16 = 32 bytes
        uint32_t a[4][4];
#pragma unroll
        for (int i = 0; i < 4; ++i) {
            const uint32_t r0 = aBase + (uint32_t)(16 * i) * (STRIDE * 2) + kOff;
            a[i][0] = lds32(r0);
            a[i][1] = lds32(r0 + 8 * (STRIDE * 2));
            a[i][2] = lds32(r0 + 16);
            a[i][3] = lds32(r0 + 8 * (STRIDE * 2) + 16);
        }
        uint32_t b[4][2];
#pragma unroll
        for (int j = 0; j < 4; ++j) {
            const uint32_t r0 = bBase + (uint32_t)(8 * j) * (STRIDE * 2) + kOff;
            b[j][0] = lds32(r0);
            b[j][1] = lds32(r0 + 16);
        }
#pragma unroll
        for (int i = 0; i < 4; ++i)
#pragma unroll
            for (int j = 0; j < 4; ++j)
                mma16816(acc[i][j], a[i], b[j]);
    }

    // ---- per-lane top-3 per owned row (8 rows x 8 values each) ----
    float tv[8][3]; int tix[8][3];
#pragma unroll
    for (int t = 0; t < 8; ++t)
#pragma unroll
        for (int s = 0; s < 3; ++s) { tv[t][s] = -3.0e38f; tix[t][s] = 0; }

    const int colBase = code0 + wn * 32 + tig * 2;
#pragma unroll
    for (int i = 0; i < 4; ++i)
#pragma unroll
        for (int j = 0; j < 4; ++j) {
            const int cb0 = colBase + j * 8;
            ins3(acc[i][j][0], cb0,     tv[2 * i],     tix[2 * i]);
            ins3(acc[i][j][1], cb0 + 1, tv[2 * i],     tix[2 * i]);
            ins3(acc[i][j][2], cb0,     tv[2 * i + 1], tix[2 * i + 1]);
            ins3(acc[i][j][3], cb0 + 1, tv[2 * i + 1], tix[2 * i + 1]);
        }

    // ---- CTA merge: 48 candidates per row -> top-8 ----
    __syncthreads();                 // tiles dead; reuse smem
    float* rv = (float*)smem;                 // [128][48]
    int*   ri = (int*)(smem + 24576);         // [128][48]
#pragma unroll
    for (int t = 0; t < 8; ++t) {
        const int rl = wm * 64 + (t >> 1) * 16 + (t & 1) * 8 + g;
        const int slot = wn * 12 + tig * 3;
#pragma unroll
        for (int s = 0; s < 3; ++s) {
            rv[rl * 48 + slot + s] = tv[t][s];
            ri[rl * 48 + slot + s] = tix[t][s];
        }
    }
    __syncthreads();

    if (tid < 128) {
        const int r = tid;
        float v[8]; int ix[8];
#pragma unroll
        for (int s = 0; s < 8; ++s) { v[s] = -3.0e38f; ix[s] = 0; }
#pragma unroll 1
        for (int q = 0; q < 48; ++q) ins8(rv[r * 48 + q], ri[r * 48 + q], v, ix);
        const size_t base = ((size_t)(row0 + r) * NTILES + blockIdx.y) * CAND;
#pragma unroll
        for (int s = 0; s < 8; ++s) { g_cval[base + s] = v[s]; g_cidx[base + s] = ix[s]; }
    }
}

// ---------------------------------------------------------------------------
// 3) finalize: merge 1024 candidates, exact fp32 rescore, softmax identity
// ---------------------------------------------------------------------------
__global__ void __launch_bounds__(128)
finalize_kernel(const float* __restrict__ x, const float* __restrict__ cb,
                float* __restrict__ out) {
    const int row = blockIdx.x;
    const int tid = threadIdx.x;
    const int wid = tid >> 5, lid = tid & 31;

    __shared__ float sv[NTILES * CAND];    // 1024
    __shared__ int   si[NTILES * CAND];
    __shared__ float s2v[256];
    __shared__ int   s2i[256];
    __shared__ int   pick[8];
    __shared__ float sex[8];
    __shared__ float sw[4];
    __shared__ int   sid[3];

    const size_t cbase = (size_t)row * NTILES * CAND;
#pragma unroll
    for (int i = tid; i < NTILES * CAND; i += 128) {
        sv[i] = g_cval[cbase + i];
        si[i] = g_cidx[cbase + i];
    }
    __syncthreads();

    // stage 1: warp 0, each lane reduces 32 candidates -> top-8
    if (wid == 0) {
        float v[8]; int ix[8];
#pragma unroll
        for (int s = 0; s < 8; ++s) { v[s] = -3.0e38f; ix[s] = 0; }
#pragma unroll 1
        for (int q = lid; q < NTILES * CAND; q += 32) ins8(sv[q], si[q], v, ix);
#pragma unroll
        for (int s = 0; s < 8; ++s) { s2v[lid * 8 + s] = v[s]; s2i[lid * 8 + s] = ix[s]; }
    }
    __syncthreads();

    // stage 2: single thread merges 256 -> top-8 pool
    if (tid == 0) {
        float v[8]; int ix[8];
#pragma unroll
        for (int s = 0; s < 8; ++s) { v[s] = -3.0e38f; ix[s] = 0; }
#pragma unroll 1
        for (int q = 0; q < 256; ++q) ins8(s2v[q], s2i[q], v, ix);
#pragma unroll
        for (int s = 0; s < 8; ++s) pick[s] = ix[s];
    }
    __syncthreads();

    // exact fp32 rescore: warp w handles candidates 2w, 2w+1
    const float4 xa = ((const float4*)(x + (size_t)row * DIM))[lid];
#pragma unroll
    for (int t = 0; t < 2; ++t) {
        const int cc = wid * 2 + t;
        const int c = pick[cc];
        const float4 ca = ((const float4*)(cb + (size_t)c * DIM))[lid];
        float p = xa.x * ca.x;
        p = fmaf(xa.y, ca.y, p);
        p = fmaf(xa.z, ca.z, p);
        p = fmaf(xa.w, ca.w, p);
#pragma unroll
        for (int o = 16; o > 0; o >>= 1) p += __shfl_xor_sync(0xFFFFFFFFu, p, o);
        if (lid == 0) sex[cc] = p;
    }
    __syncthreads();

    if (tid == 0) {
        float v[3] = { -3.0e38f, -3.0e38f, -3.0e38f };
        int ix[3] = { 0, 0, 0 };
#pragma unroll
        for (int q = 0; q < 8; ++q) ins3(sex[q], pick[q], v, ix);
        const float INV_TAU = 100.0f;
        const float m  = fmaxf(v[0], 0.0f);
        const float w0 = expf((v[0] - m) * INV_TAU);
        const float w1 = expf((v[1] - m) * INV_TAU);
        const float w2 = expf((v[2] - m) * INV_TAU);
        const float b  = expf(-m * INV_TAU);
        const float Z  = w0 + w1 + w2 + b * (float)(N_CODES - TOPK);
        const float invZ = 1.0f / Z;
        sw[0] = w0 * invZ; sw[1] = w1 * invZ; sw[2] = w2 * invZ; sw[3] = b * invZ;
        sid[0] = ix[0]; sid[1] = ix[1]; sid[2] = ix[2];
    }
    __syncthreads();

    const int d = tid;
    const float c0 = cb[(size_t)sid[0] * DIM + d];
    const float c1 = cb[(size_t)sid[1] * DIM + d];
    const float c2 = cb[(size_t)sid[2] * DIM + d];
    out[(size_t)row * DIM + d] =
        sw[0] * c0 + sw[1] * c1 + sw[2] * c2 + sw[3] * (g_cbsum[d] - c0 - c1 - c2);
}

// ---------------------------------------------------------------------------
extern "C" void kernel_launch(void* const* d_in, const int* in_sizes, int n_in,
                              void* d_out, int out_size) {
    const float* x  = (const float*)d_in[0];
    const float* cb = (const float*)d_in[1];
    if (n_in >= 2 && in_sizes[0] == N_CODES * DIM && in_sizes[1] == N_ROWS * DIM) {
        x  = (const float*)d_in[1];
        cb = (const float*)d_in[0];
    }
    float* out = (float*)d_out;

    cudaFuncSetAttribute(gemm_topk_kernel,
                         cudaFuncAttributeMaxDynamicSharedMemorySize, TILE_SMEM_BYTES);

    __nv_bfloat16 *xb_p, *cbb_p;
    cudaGetSymbolAddress((void**)&xb_p, g_xb);
    cudaGetSymbolAddress((void**)&cbb_p, g_cbb);

    convert_x_kernel<<<N_ROWS * DIM / 1024, 256>>>(x);
    convert_cb_kernel<<<128, 128>>>(cb);
    cbsum_comb_kernel<<<1, 128>>>();
    gemm_topk_kernel<<<dim3(MTILES, NTILES), 256, TILE_SMEM_BYTES>>>(xb_p, cbb_p);
    finalize_kernel<<<N_ROWS, 128>>>(x, cb, out);
}

// round 6
// speedup vs baseline: 2.6226x; 1.0180x over previous
#include <cuda_runtime.h>
#include <cuda_bf16.h>
#include <cstdint>

// ============================================================================
// MeToken: z_q = softmax(topk3_gated(x @ cb^T) / 0.01) @ cb
//
// Identity (non-topk gated scores are 0, not -inf):
//   m = max(top1, 0), w_k = exp((s_k-m)/tau), b = exp(-m/tau)
//   Z   = w0+w1+w2 + (C-K)*b
//   z_q = (w0*cb0 + w1*cb1 + w2*cb2 + b*(colsum(cb) - cb0-cb1-cb2)) / Z
//
// R5 (resubmit after infra failure): mma.sync GEMM mainloop uses
// ldmatrix.x4 (6 LDSM vs 24 LDS per k-step) and cp.async tile fill.
// Screening bf16 -> per-tile top-8 -> exact fp32 rescore of merged top-8
// pool -> closed-form softmax.
// ============================================================================

#define N_ROWS 8192
#define DIM 128
#define N_CODES 16384
#define TOPK 3

#define MT 128
#define NT 128
#define NTILES (N_CODES / NT)          // 128
#define MTILES (N_ROWS / MT)           // 64
#define CAND 8
#define STRIDE_B 272                    // bytes per smem row (136 bf16)
#define TILE_SMEM_BYTES (2 * 128 * STRIDE_B)   // 69632

// ---------------- scratch (no allocs allowed) ----------------
__device__ __nv_bfloat16 g_xb[N_ROWS * DIM];
__device__ __nv_bfloat16 g_cbb[N_CODES * DIM];
__device__ float g_part_cbsum[128 * DIM];
__device__ float g_cbsum[DIM];
__device__ float g_cval[(size_t)N_ROWS * NTILES * CAND];
__device__ int   g_cidx[(size_t)N_ROWS * NTILES * CAND];

// ---------------- helpers ----------------
__device__ __forceinline__ uint32_t smem_u32(const void* p) {
    uint32_t a;
    asm("{ .reg .u64 t; cvta.to.shared.u64 t, %1; cvt.u32.u64 %0, t; }" : "=r"(a) : "l"(p));
    return a;
}
__device__ __forceinline__ void cp_async16(uint32_t dst, const void* src) {
    asm volatile("cp.async.cg.shared.global [%0], [%1], 16;" :: "r"(dst), "l"(src) : "memory");
}
__device__ __forceinline__ void cp_async_wait_all() {
    asm volatile("cp.async.commit_group;\ncp.async.wait_group 0;" ::: "memory");
}
__device__ __forceinline__ void ldsm_x4(uint32_t& r0, uint32_t& r1, uint32_t& r2, uint32_t& r3,
                                        uint32_t addr) {
    asm volatile("ldmatrix.sync.aligned.m8n8.x4.shared.b16 {%0,%1,%2,%3}, [%4];"
                 : "=r"(r0), "=r"(r1), "=r"(r2), "=r"(r3) : "r"(addr));
}
__device__ __forceinline__ void mma16816(float c[4], const uint32_t a[4], const uint32_t b[2]) {
    asm volatile(
        "mma.sync.aligned.m16n8k16.row.col.f32.bf16.bf16.f32 "
        "{%0,%1,%2,%3}, {%4,%5,%6,%7}, {%8,%9}, {%0,%1,%2,%3};"
        : "+f"(c[0]), "+f"(c[1]), "+f"(c[2]), "+f"(c[3])
        : "r"(a[0]), "r"(a[1]), "r"(a[2]), "r"(a[3]), "r"(b[0]), "r"(b[1]));
}
__device__ __forceinline__ void ins8(float s, int c, float v[8], int ix[8]) {
    if (s <= v[7]) return;
    v[7] = s; ix[7] = c;
#pragma unroll
    for (int t = 7; t > 0; --t) {
        if (v[t] > v[t - 1]) {
            float tv = v[t]; v[t] = v[t - 1]; v[t - 1] = tv;
            int ti = ix[t]; ix[t] = ix[t - 1]; ix[t - 1] = ti;
        }
    }
}
__device__ __forceinline__ void ins3(float s, int c, float v[3], int ix[3]) {
    if (s > v[2]) {
        if (s > v[1]) {
            v[2] = v[1]; ix[2] = ix[1];
            if (s > v[0]) { v[1] = v[0]; ix[1] = ix[0]; v[0] = s; ix[0] = c; }
            else          { v[1] = s;    ix[1] = c; }
        } else { v[2] = s; ix[2] = c; }
    }
}

// ---------------------------------------------------------------------------
// 1) converts + column sums
// ---------------------------------------------------------------------------
__global__ void convert_x_kernel(const float* __restrict__ x) {
    const int i = (blockIdx.x * 256 + threadIdx.x) * 4;
    const float4 v = *(const float4*)(x + i);
    __nv_bfloat162* o = (__nv_bfloat162*)(g_xb + i);
    o[0] = __nv_bfloat162(__float2bfloat16_rn(v.x), __float2bfloat16_rn(v.y));
    o[1] = __nv_bfloat162(__float2bfloat16_rn(v.z), __float2bfloat16_rn(v.w));
}
__global__ void convert_cb_kernel(const float* __restrict__ cb) {
    const int b = blockIdx.x;   // 128 blocks x 128 codes each
    const int d = threadIdx.x;  // column
    const float* p = cb + (size_t)b * 128 * DIM + d;
    __nv_bfloat16* q = g_cbb + (size_t)b * 128 * DIM + d;
    float s = 0.0f;
#pragma unroll 8
    for (int c = 0; c < 128; ++c) {
        const float v = p[(size_t)c * DIM];
        s += v;
        q[(size_t)c * DIM] = __float2bfloat16_rn(v);
    }
    g_part_cbsum[b * DIM + d] = s;
}
__global__ void cbsum_comb_kernel() {
    const int d = threadIdx.x;
    float s = 0.0f;
#pragma unroll 8
    for (int b = 0; b < 128; ++b) s += g_part_cbsum[b * DIM + d];
    g_cbsum[d] = s;
}

// ---------------------------------------------------------------------------
// 2) mma.sync bf16 GEMM (CTA 128x128, K=128) + fused per-row top-8
//    8 warps = 2(M) x 4(N); warp tile 64x32; ldmatrix fragment loads
// ---------------------------------------------------------------------------
__global__ void __launch_bounds__(256, 2)
gemm_topk_kernel(const __nv_bfloat16* __restrict__ xb,
                 const __nv_bfloat16* __restrict__ cbb) {
    extern __shared__ __align__(16) char smem[];
    const uint32_t sbase = smem_u32(smem);
    const uint32_t sA = sbase;
    const uint32_t sB = sbase + 128 * STRIDE_B;

    const int tid = threadIdx.x;
    const int wid = tid >> 5, lane = tid & 31;
    const int g = lane >> 2, tig = lane & 3;
    const int wm = wid & 1, wn = wid >> 1;

    const int row0  = blockIdx.x * MT;
    const int code0 = blockIdx.y * NT;

    // ---- fill tiles via cp.async: 128 rows x 16 x 16B each ----
    {
        const uint4* gx = (const uint4*)(xb + (size_t)row0 * DIM);
        const uint4* gc = (const uint4*)(cbb + (size_t)code0 * DIM);
#pragma unroll
        for (int i = tid; i < 128 * 16; i += 256) {
            const int r = i >> 4, kc = i & 15;
            cp_async16(sA + r * STRIDE_B + kc * 16, gx + r * 16 + kc);
        }
#pragma unroll
        for (int i = tid; i < 128 * 16; i += 256) {
            const int r = i >> 4, kc = i & 15;
            cp_async16(sB + r * STRIDE_B + kc * 16, gc + r * 16 + kc);
        }
        cp_async_wait_all();
    }
    __syncthreads();

    float acc[4][4][4];
#pragma unroll
    for (int i = 0; i < 4; ++i)
#pragma unroll
        for (int j = 0; j < 4; ++j)
#pragma unroll
            for (int c = 0; c < 4; ++c) acc[i][j][c] = 0.0f;

    // ldmatrix per-lane source addresses
    // A frag i (16x16): m0 rows +0-7 col0 | m1 rows +8-15 col0 | m2 rows +0-7 col16B | m3 rows +8-15 col16B
    const int aq = lane >> 3;                   // matrix id 0..3
    const uint32_t aRow = (uint32_t)(wm * 64 + (lane & 7) + (aq & 1) * 8);
    const uint32_t aCol = (uint32_t)((aq >> 1) * 16);
    uint32_t aAddr[4];
#pragma unroll
    for (int i = 0; i < 4; ++i)
        aAddr[i] = sA + (aRow + 16 * i) * STRIDE_B + aCol;

    // B frag pair jp (covers j=2jp,2jp+1): m0 rows +0-7 col0 | m1 rows +0-7 col16B |
    //                                      m2 rows +8-15 col0 | m3 rows +8-15 col16B
    const uint32_t bRow = (uint32_t)(wn * 32 + (lane & 7) + (aq >> 1) * 8);
    const uint32_t bCol = (uint32_t)((aq & 1) * 16);
    uint32_t bAddr[2];
#pragma unroll
    for (int jp = 0; jp < 2; ++jp)
        bAddr[jp] = sB + (bRow + 16 * jp) * STRIDE_B + bCol;

#pragma unroll
    for (int ks = 0; ks < 8; ++ks) {
        const uint32_t kOff = ks * 32;   // 16 bf16 = 32 bytes
        uint32_t a[4][4];
#pragma unroll
        for (int i = 0; i < 4; ++i)
            ldsm_x4(a[i][0], a[i][1], a[i][2], a[i][3], aAddr[i] + kOff);
        uint32_t b[4][2];
#pragma unroll
        for (int jp = 0; jp < 2; ++jp)
            ldsm_x4(b[2 * jp][0], b[2 * jp][1], b[2 * jp + 1][0], b[2 * jp + 1][1],
                    bAddr[jp] + kOff);
#pragma unroll
        for (int i = 0; i < 4; ++i)
#pragma unroll
            for (int j = 0; j < 4; ++j)
                mma16816(acc[i][j], a[i], b[j]);
    }

    // ---- per-lane top-3 per owned row (8 rows x 8 values each) ----
    float tv[8][3]; int tix[8][3];
#pragma unroll
    for (int t = 0; t < 8; ++t)
#pragma unroll
        for (int s = 0; s < 3; ++s) { tv[t][s] = -3.0e38f; tix[t][s] = 0; }

    const int colBase = code0 + wn * 32 + tig * 2;
#pragma unroll
    for (int i = 0; i < 4; ++i)
#pragma unroll
        for (int j = 0; j < 4; ++j) {
            const int cb0 = colBase + j * 8;
            ins3(acc[i][j][0], cb0,     tv[2 * i],     tix[2 * i]);
            ins3(acc[i][j][1], cb0 + 1, tv[2 * i],     tix[2 * i]);
            ins3(acc[i][j][2], cb0,     tv[2 * i + 1], tix[2 * i + 1]);
            ins3(acc[i][j][3], cb0 + 1, tv[2 * i + 1], tix[2 * i + 1]);
        }

    // ---- CTA merge: 48 candidates per row -> top-8 ----
    __syncthreads();                 // tiles dead; reuse smem
    float* rv = (float*)smem;                 // [128][48]
    int*   ri = (int*)(smem + 24576);         // [128][48]
#pragma unroll
    for (int t = 0; t < 8; ++t) {
        const int rl = wm * 64 + (t >> 1) * 16 + (t & 1) * 8 + g;
        const int slot = wn * 12 + tig * 3;
#pragma unroll
        for (int s = 0; s < 3; ++s) {
            rv[rl * 48 + slot + s] = tv[t][s];
            ri[rl * 48 + slot + s] = tix[t][s];
        }
    }
    __syncthreads();

    if (tid < 128) {
        const int r = tid;
        float v[8]; int ix[8];
#pragma unroll
        for (int s = 0; s < 8; ++s) { v[s] = -3.0e38f; ix[s] = 0; }
#pragma unroll 1
        for (int q = 0; q < 48; ++q) ins8(rv[r * 48 + q], ri[r * 48 + q], v, ix);
        const size_t base = ((size_t)(row0 + r) * NTILES + blockIdx.y) * CAND;
#pragma unroll
        for (int s = 0; s < 8; ++s) { g_cval[base + s] = v[s]; g_cidx[base + s] = ix[s]; }
    }
}

// ---------------------------------------------------------------------------
// 3) finalize: merge 1024 candidates, exact fp32 rescore, softmax identity
// ---------------------------------------------------------------------------
__global__ void __launch_bounds__(128)
finalize_kernel(const float* __restrict__ x, const float* __restrict__ cb,
                float* __restrict__ out) {
    const int row = blockIdx.x;
    const int tid = threadIdx.x;
    const int wid = tid >> 5, lid = tid & 31;

    __shared__ float sv[NTILES * CAND];    // 1024
    __shared__ int   si[NTILES * CAND];
    __shared__ float s2v[256];
    __shared__ int   s2i[256];
    __shared__ int   pick[8];
    __shared__ float sex[8];
    __shared__ float sw[4];
    __shared__ int   sid[3];

    const size_t cbase = (size_t)row * NTILES * CAND;
#pragma unroll
    for (int i = tid; i < NTILES * CAND; i += 128) {
        sv[i] = g_cval[cbase + i];
        si[i] = g_cidx[cbase + i];
    }
    __syncthreads();

    // stage 1: warp 0, each lane reduces 32 candidates -> top-8
    if (wid == 0) {
        float v[8]; int ix[8];
#pragma unroll
        for (int s = 0; s < 8; ++s) { v[s] = -3.0e38f; ix[s] = 0; }
#pragma unroll 1
        for (int q = lid; q < NTILES * CAND; q += 32) ins8(sv[q], si[q], v, ix);
#pragma unroll
        for (int s = 0; s < 8; ++s) { s2v[lid * 8 + s] = v[s]; s2i[lid * 8 + s] = ix[s]; }
    }
    __syncthreads();

    // stage 2: single thread merges 256 -> top-8 pool
    if (tid == 0) {
        float v[8]; int ix[8];
#pragma unroll
        for (int s = 0; s < 8; ++s) { v[s] = -3.0e38f; ix[s] = 0; }
#pragma unroll 1
        for (int q = 0; q < 256; ++q) ins8(s2v[q], s2i[q], v, ix);
#pragma unroll
        for (int s = 0; s < 8; ++s) pick[s] = ix[s];
    }
    __syncthreads();

    // exact fp32 rescore: warp w handles candidates 2w, 2w+1
    const float4 xa = ((const float4*)(x + (size_t)row * DIM))[lid];
#pragma unroll
    for (int t = 0; t < 2; ++t) {
        const int cc = wid * 2 + t;
        const int c = pick[cc];
        const float4 ca = ((const float4*)(cb + (size_t)c * DIM))[lid];
        float p = xa.x * ca.x;
        p = fmaf(xa.y, ca.y, p);
        p = fmaf(xa.z, ca.z, p);
        p = fmaf(xa.w, ca.w, p);
#pragma unroll
        for (int o = 16; o > 0; o >>= 1) p += __shfl_xor_sync(0xFFFFFFFFu, p, o);
        if (lid == 0) sex[cc] = p;
    }
    __syncthreads();

    if (tid == 0) {
        float v[3] = { -3.0e38f, -3.0e38f, -3.0e38f };
        int ix[3] = { 0, 0, 0 };
#pragma unroll
        for (int q = 0; q < 8; ++q) ins3(sex[q], pick[q], v, ix);
        const float INV_TAU = 100.0f;
        const float m  = fmaxf(v[0], 0.0f);
        const float w0 = expf((v[0] - m) * INV_TAU);
        const float w1 = expf((v[1] - m) * INV_TAU);
        const float w2 = expf((v[2] - m) * INV_TAU);
        const float b  = expf(-m * INV_TAU);
        const float Z  = w0 + w1 + w2 + b * (float)(N_CODES - TOPK);
        const float invZ = 1.0f / Z;
        sw[0] = w0 * invZ; sw[1] = w1 * invZ; sw[2] = w2 * invZ; sw[3] = b * invZ;
        sid[0] = ix[0]; sid[1] = ix[1]; sid[2] = ix[2];
    }
    __syncthreads();

    const int d = tid;
    const float c0 = cb[(size_t)sid[0] * DIM + d];
    const float c1 = cb[(size_t)sid[1] * DIM + d];
    const float c2 = cb[(size_t)sid[2] * DIM + d];
    out[(size_t)row * DIM + d] =
        sw[0] * c0 + sw[1] * c1 + sw[2] * c2 + sw[3] * (g_cbsum[d] - c0 - c1 - c2);
}

// ---------------------------------------------------------------------------
extern "C" void kernel_launch(void* const* d_in, const int* in_sizes, int n_in,
                              void* d_out, int out_size) {
    const float* x  = (const float*)d_in[0];
    const float* cb = (const float*)d_in[1];
    if (n_in >= 2 && in_sizes[0] == N_CODES * DIM && in_sizes[1] == N_ROWS * DIM) {
        x  = (const float*)d_in[1];
        cb = (const float*)d_in[0];
    }
    float* out = (float*)d_out;

    cudaFuncSetAttribute(gemm_topk_kernel,
                         cudaFuncAttributeMaxDynamicSharedMemorySize, TILE_SMEM_BYTES);

    __nv_bfloat16 *xb_p, *cbb_p;
    cudaGetSymbolAddress((void**)&xb_p, g_xb);
    cudaGetSymbolAddress((void**)&cbb_p, g_cbb);

    convert_x_kernel<<<N_ROWS * DIM / 1024, 256>>>(x);
    convert_cb_kernel<<<128, 128>>>(cb);
    cbsum_comb_kernel<<<1, 128>>>();
    gemm_topk_kernel<<<dim3(MTILES, NTILES), 256, TILE_SMEM_BYTES>>>(xb_p, cbb_p);
    finalize_kernel<<<N_ROWS, 128>>>(x, cb, out);
}

// round 7
// speedup vs baseline: 3.9853x; 1.5196x over previous
#include <cuda_runtime.h>
#include <cuda_bf16.h>
#include <cstdint>

// ============================================================================
// MeToken: z_q = softmax(topk3_gated(x @ cb^T) / 0.01) @ cb
//
// Identity (non-topk gated scores are 0, not -inf):
//   m = max(top1, 0), w_k = exp((s_k-m)/tau), b = exp(-m/tau)
//   Z   = w0+w1+w2 + (C-K)*b
//   z_q = (w0*cb0 + w1*cb1 + w2*cb2 + b*(colsum(cb) - cb0-cb1-cb2)) / Z
//
// R7: multi-tile CTAs. Each CTA keeps its A tile (128 rows) resident and
// streams 8 B-subtiles (1024 codes) through a double-buffered cp.async
// pipeline; top-3 state lives in registers across the whole group; one
// CTA merge at the end. Amortizes fill latency, epilogue, and candidate
// traffic 8x vs R6.
// ============================================================================

#define N_ROWS 8192
#define DIM 128
#define N_CODES 16384
#define TOPK 3

#define MT 128
#define NT 128                          // codes per B-subtile
#define TILES_PER_GROUP 8
#define GROUP_CODES (NT * TILES_PER_GROUP)   // 1024
#define NGROUPS (N_CODES / GROUP_CODES)      // 16
#define MTILES (N_ROWS / MT)                 // 64
#define CAND 8
#define STRIDE_B 272                    // bytes per smem row (136 bf16)
#define A_BYTES (128 * STRIDE_B)        // 34816
#define B_BYTES (128 * STRIDE_B)        // 34816
#define GEMM_SMEM (A_BYTES + 2 * B_BYTES)    // 104448

// ---------------- scratch (no allocs allowed) ----------------
__device__ __nv_bfloat16 g_xb[N_ROWS * DIM];
__device__ __nv_bfloat16 g_cbb[N_CODES * DIM];
__device__ float g_part_cbsum[128 * DIM];
__device__ float g_cbsum[DIM];
__device__ float g_cval[(size_t)N_ROWS * NGROUPS * CAND];
__device__ int   g_cidx[(size_t)N_ROWS * NGROUPS * CAND];

// ---------------- helpers ----------------
__device__ __forceinline__ uint32_t smem_u32(const void* p) {
    uint32_t a;
    asm("{ .reg .u64 t; cvta.to.shared.u64 t, %1; cvt.u32.u64 %0, t; }" : "=r"(a) : "l"(p));
    return a;
}
__device__ __forceinline__ void cp_async16(uint32_t dst, const void* src) {
    asm volatile("cp.async.cg.shared.global [%0], [%1], 16;" :: "r"(dst), "l"(src) : "memory");
}
__device__ __forceinline__ void cp_commit() {
    asm volatile("cp.async.commit_group;" ::: "memory");
}
__device__ __forceinline__ void cp_wait1() {
    asm volatile("cp.async.wait_group 1;" ::: "memory");
}
__device__ __forceinline__ void cp_wait0() {
    asm volatile("cp.async.wait_group 0;" ::: "memory");
}
__device__ __forceinline__ void ldsm_x4(uint32_t& r0, uint32_t& r1, uint32_t& r2, uint32_t& r3,
                                        uint32_t addr) {
    asm volatile("ldmatrix.sync.aligned.m8n8.x4.shared.b16 {%0,%1,%2,%3}, [%4];"
                 : "=r"(r0), "=r"(r1), "=r"(r2), "=r"(r3) : "r"(addr));
}
__device__ __forceinline__ void mma16816(float c[4], const uint32_t a[4], const uint32_t b[2]) {
    asm volatile(
        "mma.sync.aligned.m16n8k16.row.col.f32.bf16.bf16.f32 "
        "{%0,%1,%2,%3}, {%4,%5,%6,%7}, {%8,%9}, {%0,%1,%2,%3};"
        : "+f"(c[0]), "+f"(c[1]), "+f"(c[2]), "+f"(c[3])
        : "r"(a[0]), "r"(a[1]), "r"(a[2]), "r"(a[3]), "r"(b[0]), "r"(b[1]));
}
__device__ __forceinline__ void ins8(float s, int c, float v[8], int ix[8]) {
    if (s <= v[7]) return;
    v[7] = s; ix[7] = c;
#pragma unroll
    for (int t = 7; t > 0; --t) {
        if (v[t] > v[t - 1]) {
            float tv = v[t]; v[t] = v[t - 1]; v[t - 1] = tv;
            int ti = ix[t]; ix[t] = ix[t - 1]; ix[t - 1] = ti;
        }
    }
}
__device__ __forceinline__ void ins3(float s, int c, float v[3], int ix[3]) {
    if (s > v[2]) {
        if (s > v[1]) {
            v[2] = v[1]; ix[2] = ix[1];
            if (s > v[0]) { v[1] = v[0]; ix[1] = ix[0]; v[0] = s; ix[0] = c; }
            else          { v[1] = s;    ix[1] = c; }
        } else { v[2] = s; ix[2] = c; }
    }
}

// ---------------------------------------------------------------------------
// 1) converts + column sums
// ---------------------------------------------------------------------------
__global__ void convert_x_kernel(const float* __restrict__ x) {
    const int i = (blockIdx.x * 256 + threadIdx.x) * 4;
    const float4 v = *(const float4*)(x + i);
    __nv_bfloat162* o = (__nv_bfloat162*)(g_xb + i);
    o[0] = __nv_bfloat162(__float2bfloat16_rn(v.x), __float2bfloat16_rn(v.y));
    o[1] = __nv_bfloat162(__float2bfloat16_rn(v.z), __float2bfloat16_rn(v.w));
}
__global__ void convert_cb_kernel(const float* __restrict__ cb) {
    const int b = blockIdx.x;   // 128 blocks x 128 codes each
    const int d = threadIdx.x;  // column
    const float* p = cb + (size_t)b * 128 * DIM + d;
    __nv_bfloat16* q = g_cbb + (size_t)b * 128 * DIM + d;
    float s = 0.0f;
#pragma unroll 8
    for (int c = 0; c < 128; ++c) {
        const float v = p[(size_t)c * DIM];
        s += v;
        q[(size_t)c * DIM] = __float2bfloat16_rn(v);
    }
    g_part_cbsum[b * DIM + d] = s;
}
__global__ void cbsum_comb_kernel() {
    const int d = threadIdx.x;
    float s = 0.0f;
#pragma unroll 8
    for (int b = 0; b < 128; ++b) s += g_part_cbsum[b * DIM + d];
    g_cbsum[d] = s;
}

// ---------------------------------------------------------------------------
// 2) multi-tile mma.sync GEMM: A resident, 8 double-buffered B-subtiles,
//    fused per-row top-3 (regs) across group, one CTA merge -> top-8/group
// ---------------------------------------------------------------------------
__global__ void __launch_bounds__(256, 1)
gemm_topk_kernel(const __nv_bfloat16* __restrict__ xb,
                 const __nv_bfloat16* __restrict__ cbb) {
    extern __shared__ __align__(16) char smem[];
    const uint32_t sbase = smem_u32(smem);
    const uint32_t sA = sbase;
    const uint32_t sB[2] = { sbase + A_BYTES, sbase + A_BYTES + B_BYTES };

    const int tid = threadIdx.x;
    const int wid = tid >> 5, lane = tid & 31;
    const int g = lane >> 2, tig = lane & 3;
    const int wm = wid & 1, wn = wid >> 1;

    const int row0  = blockIdx.x * MT;
    const int code0 = blockIdx.y * GROUP_CODES;

    const uint4* gx = (const uint4*)(xb + (size_t)row0 * DIM);
    const uint4* gc = (const uint4*)(cbb + (size_t)code0 * DIM);

    // ---- prologue: A + B0 (group 0) ----
#pragma unroll
    for (int i = tid; i < 128 * 16; i += 256) {
        const int r = i >> 4, kc = i & 15;
        cp_async16(sA + r * STRIDE_B + kc * 16, gx + r * 16 + kc);
    }
#pragma unroll
    for (int i = tid; i < 128 * 16; i += 256) {
        const int r = i >> 4, kc = i & 15;
        cp_async16(sB[0] + r * STRIDE_B + kc * 16, gc + r * 16 + kc);
    }
    cp_commit();

    // per-lane top-3 state for 8 owned rows, carried across all tiles
    float tv[8][3]; int tix[8][3];
#pragma unroll
    for (int t = 0; t < 8; ++t)
#pragma unroll
        for (int s = 0; s < 3; ++s) { tv[t][s] = -3.0e38f; tix[t][s] = 0; }

    // ldmatrix per-lane addresses (offsets inside a tile)
    const int aq = lane >> 3;
    const uint32_t aRow = (uint32_t)(wm * 64 + (lane & 7) + (aq & 1) * 8);
    const uint32_t aCol = (uint32_t)((aq >> 1) * 16);
    uint32_t aAddr[4];
#pragma unroll
    for (int i = 0; i < 4; ++i)
        aAddr[i] = sA + (aRow + 16 * i) * STRIDE_B + aCol;
    const uint32_t bRowOff = (uint32_t)((wn * 32 + (lane & 7) + (aq >> 1) * 8)) * STRIDE_B
                           + (uint32_t)((aq & 1) * 16);

#pragma unroll 1
    for (int t = 0; t < TILES_PER_GROUP; ++t) {
        // prefetch next B-subtile into the buffer freed at iteration t-1
        __syncthreads();
        if (t + 1 < TILES_PER_GROUP) {
            const uint4* gt = gc + (size_t)(t + 1) * 128 * 16;
            const uint32_t dst = sB[(t + 1) & 1];
#pragma unroll
            for (int i = tid; i < 128 * 16; i += 256) {
                const int r = i >> 4, kc = i & 15;
                cp_async16(dst + r * STRIDE_B + kc * 16, gt + r * 16 + kc);
            }
            cp_commit();
            cp_wait1();          // tile t's group complete
        } else {
            cp_wait0();
        }
        __syncthreads();

        float acc[4][4][4];
#pragma unroll
        for (int i = 0; i < 4; ++i)
#pragma unroll
            for (int j = 0; j < 4; ++j)
#pragma unroll
                for (int c = 0; c < 4; ++c) acc[i][j][c] = 0.0f;

        const uint32_t bBase = sB[t & 1] + bRowOff;
#pragma unroll
        for (int ks = 0; ks < 8; ++ks) {
            const uint32_t kOff = ks * 32;
            uint32_t a[4][4];
#pragma unroll
            for (int i = 0; i < 4; ++i)
                ldsm_x4(a[i][0], a[i][1], a[i][2], a[i][3], aAddr[i] + kOff);
            uint32_t b[4][2];
#pragma unroll
            for (int jp = 0; jp < 2; ++jp)
                ldsm_x4(b[2 * jp][0], b[2 * jp][1], b[2 * jp + 1][0], b[2 * jp + 1][1],
                        bBase + (uint32_t)(16 * jp) * STRIDE_B + kOff);
#pragma unroll
            for (int i = 0; i < 4; ++i)
#pragma unroll
                for (int j = 0; j < 4; ++j)
                    mma16816(acc[i][j], a[i], b[j]);
        }

        // fold tile scores into per-lane top-3
        const int colBase = code0 + t * NT + wn * 32 + tig * 2;
#pragma unroll
        for (int i = 0; i < 4; ++i)
#pragma unroll
            for (int j = 0; j < 4; ++j) {
                const int cb0 = colBase + j * 8;
                ins3(acc[i][j][0], cb0,     tv[2 * i],     tix[2 * i]);
                ins3(acc[i][j][1], cb0 + 1, tv[2 * i],     tix[2 * i]);
                ins3(acc[i][j][2], cb0,     tv[2 * i + 1], tix[2 * i + 1]);
                ins3(acc[i][j][3], cb0 + 1, tv[2 * i + 1], tix[2 * i + 1]);
            }
    }

    // ---- CTA merge (once per group): 48 candidates/row -> top-8 ----
    __syncthreads();
    float* rv = (float*)smem;                 // [128][48] = 24576 B
    int*   ri = (int*)(smem + 24576);         // [128][48]
#pragma unroll
    for (int t = 0; t < 8; ++t) {
        const int rl = wm * 64 + (t >> 1) * 16 + (t & 1) * 8 + g;
        const int slot = wn * 12 + tig * 3;
#pragma unroll
        for (int s = 0; s < 3; ++s) {
            rv[rl * 48 + slot + s] = tv[t][s];
            ri[rl * 48 + slot + s] = tix[t][s];
        }
    }
    __syncthreads();

    if (tid < 128) {
        const int r = tid;
        float v[8]; int ix[8];
#pragma unroll
        for (int s = 0; s < 8; ++s) { v[s] = -3.0e38f; ix[s] = 0; }
#pragma unroll 1
        for (int q = 0; q < 48; ++q) ins8(rv[r * 48 + q], ri[r * 48 + q], v, ix);
        const size_t base = ((size_t)(row0 + r) * NGROUPS + blockIdx.y) * CAND;
#pragma unroll
        for (int s = 0; s < 8; ++s) { g_cval[base + s] = v[s]; g_cidx[base + s] = ix[s]; }
    }
}

// ---------------------------------------------------------------------------
// 3) finalize: merge 128 candidates, exact fp32 rescore, softmax identity
// ---------------------------------------------------------------------------
__global__ void __launch_bounds__(128)
finalize_kernel(const float* __restrict__ x, const float* __restrict__ cb,
                float* __restrict__ out) {
    const int row = blockIdx.x;
    const int tid = threadIdx.x;
    const int wid = tid >> 5, lid = tid & 31;

    __shared__ float sv[NGROUPS * CAND];   // 128
    __shared__ int   si[NGROUPS * CAND];
    __shared__ float s2v[64];
    __shared__ int   s2i[64];
    __shared__ int   pick[8];
    __shared__ float sex[8];
    __shared__ float sw[4];
    __shared__ int   sid[3];

    const size_t cbase = (size_t)row * NGROUPS * CAND;
    if (tid < NGROUPS * CAND) {
        sv[tid] = g_cval[cbase + tid];
        si[tid] = g_cidx[cbase + tid];
    }
    __syncthreads();

    // stage 1: 8 lanes of warp 0, each reduces 16 candidates -> top-8
    if (wid == 0 && lid < 8) {
        float v[8]; int ix[8];
#pragma unroll
        for (int s = 0; s < 8; ++s) { v[s] = -3.0e38f; ix[s] = 0; }
#pragma unroll 1
        for (int q = lid; q < NGROUPS * CAND; q += 8) ins8(sv[q], si[q], v, ix);
#pragma unroll
        for (int s = 0; s < 8; ++s) { s2v[lid * 8 + s] = v[s]; s2i[lid * 8 + s] = ix[s]; }
    }
    __syncthreads();

    // stage 2: single thread merges 64 -> top-8 pool
    if (tid == 0) {
        float v[8]; int ix[8];
#pragma unroll
        for (int s = 0; s < 8; ++s) { v[s] = -3.0e38f; ix[s] = 0; }
#pragma unroll 1
        for (int q = 0; q < 64; ++q) ins8(s2v[q], s2i[q], v, ix);
#pragma unroll
        for (int s = 0; s < 8; ++s) pick[s] = ix[s];
    }
    __syncthreads();

    // exact fp32 rescore: warp w handles candidates 2w, 2w+1
    const float4 xa = ((const float4*)(x + (size_t)row * DIM))[lid];
#pragma unroll
    for (int t = 0; t < 2; ++t) {
        const int cc = wid * 2 + t;
        const int c = pick[cc];
        const float4 ca = ((const float4*)(cb + (size_t)c * DIM))[lid];
        float p = xa.x * ca.x;
        p = fmaf(xa.y, ca.y, p);
        p = fmaf(xa.z, ca.z, p);
        p = fmaf(xa.w, ca.w, p);
#pragma unroll
        for (int o = 16; o > 0; o >>= 1) p += __shfl_xor_sync(0xFFFFFFFFu, p, o);
        if (lid == 0) sex[cc] = p;
    }
    __syncthreads();

    if (tid == 0) {
        float v[3] = { -3.0e38f, -3.0e38f, -3.0e38f };
        int ix[3] = { 0, 0, 0 };
#pragma unroll
        for (int q = 0; q < 8; ++q) ins3(sex[q], pick[q], v, ix);
        const float INV_TAU = 100.0f;
        const float m  = fmaxf(v[0], 0.0f);
        const float w0 = expf((v[0] - m) * INV_TAU);
        const float w1 = expf((v[1] - m) * INV_TAU);
        const float w2 = expf((v[2] - m) * INV_TAU);
        const float b  = expf(-m * INV_TAU);
        const float Z  = w0 + w1 + w2 + b * (float)(N_CODES - TOPK);
        const float invZ = 1.0f / Z;
        sw[0] = w0 * invZ; sw[1] = w1 * invZ; sw[2] = w2 * invZ; sw[3] = b * invZ;
        sid[0] = ix[0]; sid[1] = ix[1]; sid[2] = ix[2];
    }
    __syncthreads();

    const int d = tid;
    const float c0 = cb[(size_t)sid[0] * DIM + d];
    const float c1 = cb[(size_t)sid[1] * DIM + d];
    const float c2 = cb[(size_t)sid[2] * DIM + d];
    out[(size_t)row * DIM + d] =
        sw[0] * c0 + sw[1] * c1 + sw[2] * c2 + sw[3] * (g_cbsum[d] - c0 - c1 - c2);
}

// ---------------------------------------------------------------------------
extern "C" void kernel_launch(void* const* d_in, const int* in_sizes, int n_in,
                              void* d_out, int out_size) {
    const float* x  = (const float*)d_in[0];
    const float* cb = (const float*)d_in[1];
    if (n_in >= 2 && in_sizes[0] == N_CODES * DIM && in_sizes[1] == N_ROWS * DIM) {
        x  = (const float*)d_in[1];
        cb = (const float*)d_in[0];
    }
    float* out = (float*)d_out;

    cudaFuncSetAttribute(gemm_topk_kernel,
                         cudaFuncAttributeMaxDynamicSharedMemorySize, GEMM_SMEM);

    __nv_bfloat16 *xb_p, *cbb_p;
    cudaGetSymbolAddress((void**)&xb_p, g_xb);
    cudaGetSymbolAddress((void**)&cbb_p, g_cbb);

    convert_x_kernel<<<N_ROWS * DIM / 1024, 256>>>(x);
    convert_cb_kernel<<<128, 128>>>(cb);
    cbsum_comb_kernel<<<1, 128>>>();
    gemm_topk_kernel<<<dim3(MTILES, NGROUPS), 256, GEMM_SMEM>>>(xb_p, cbb_p);
    finalize_kernel<<<N_ROWS, 128>>>(x, cb, out);
}

// round 8
// speedup vs baseline: 6.5421x; 1.6415x over previous
#include <cuda_runtime.h>
#include <cuda_bf16.h>
#include <cstdint>

// ============================================================================
// MeToken: z_q = softmax(topk3_gated(x @ cb^T) / 0.01) @ cb
//
// Identity (non-topk gated scores are 0, not -inf):
//   m = max(top1, 0), w_k = exp((s_k-m)/tau), b = exp(-m/tau)
//   Z   = w0+w1+w2 + (C-K)*b
//   z_q = (w0*cb0 + w1*cb1 + w2*cb2 + b*(colsum(cb) - cb0-cb1-cb2)) / Z
//
// R8: 2 CTAs/SM. Top-3 screening state packed into u32 keys (monotone fp32
// bits, low 10 bits = group-local code idx) -> 12 regs instead of 48; warp
// tile 32x64 (4M x 2N); __launch_bounds__(256,2). Exact fp32 rescore of the
// merged top-8 pool unchanged.
// ============================================================================

#define N_ROWS 8192
#define DIM 128
#define N_CODES 16384
#define TOPK 3

#define MT 128
#define NT 128                          // codes per B-subtile
#define TILES_PER_GROUP 8
#define GROUP_CODES (NT * TILES_PER_GROUP)   // 1024
#define NGROUPS (N_CODES / GROUP_CODES)      // 16
#define MTILES (N_ROWS / MT)                 // 64
#define CAND 8
#define STRIDE_B 272                    // bytes per smem row (136 bf16)
#define A_BYTES (128 * STRIDE_B)        // 34816
#define B_BYTES (128 * STRIDE_B)        // 34816
#define GEMM_SMEM (A_BYTES + 2 * B_BYTES)    // 104448

// ---------------- scratch (no allocs allowed) ----------------
__device__ __nv_bfloat16 g_xb[N_ROWS * DIM];
__device__ __nv_bfloat16 g_cbb[N_CODES * DIM];
__device__ float g_part_cbsum[128 * DIM];
__device__ float g_cbsum[DIM];
__device__ uint32_t g_ckey[(size_t)N_ROWS * NGROUPS * CAND];   // packed keys

// ---------------- helpers ----------------
__device__ __forceinline__ uint32_t smem_u32(const void* p) {
    uint32_t a;
    asm("{ .reg .u64 t; cvta.to.shared.u64 t, %1; cvt.u32.u64 %0, t; }" : "=r"(a) : "l"(p));
    return a;
}
__device__ __forceinline__ void cp_async16(uint32_t dst, const void* src) {
    asm volatile("cp.async.cg.shared.global [%0], [%1], 16;" :: "r"(dst), "l"(src) : "memory");
}
__device__ __forceinline__ void cp_commit() {
    asm volatile("cp.async.commit_group;" ::: "memory");
}
__device__ __forceinline__ void cp_wait1() {
    asm volatile("cp.async.wait_group 1;" ::: "memory");
}
__device__ __forceinline__ void cp_wait0() {
    asm volatile("cp.async.wait_group 0;" ::: "memory");
}
__device__ __forceinline__ void ldsm_x4(uint32_t& r0, uint32_t& r1, uint32_t& r2, uint32_t& r3,
                                        uint32_t addr) {
    asm volatile("ldmatrix.sync.aligned.m8n8.x4.shared.b16 {%0,%1,%2,%3}, [%4];"
                 : "=r"(r0), "=r"(r1), "=r"(r2), "=r"(r3) : "r"(addr));
}
__device__ __forceinline__ void mma16816(float c[4], const uint32_t a[4], const uint32_t b[2]) {
    asm volatile(
        "mma.sync.aligned.m16n8k16.row.col.f32.bf16.bf16.f32 "
        "{%0,%1,%2,%3}, {%4,%5,%6,%7}, {%8,%9}, {%0,%1,%2,%3};"
        : "+f"(c[0]), "+f"(c[1]), "+f"(c[2]), "+f"(c[3])
        : "r"(a[0]), "r"(a[1]), "r"(a[2]), "r"(a[3]), "r"(b[0]), "r"(b[1]));
}

// monotone fp32 -> u32 key; low 10 bits carry group-local code index
__device__ __forceinline__ uint32_t pack_key(float s, int lidx) {
    uint32_t u = __float_as_uint(s);
    u ^= (uint32_t)((int32_t)u >> 31) | 0x80000000u;
    return (u & 0xFFFFFC00u) | (uint32_t)lidx;
}
__device__ __forceinline__ void insk3(uint32_t k, uint32_t v[3]) {
    if (k > v[2]) {
        if (k > v[1]) {
            v[2] = v[1];
            if (k > v[0]) { v[1] = v[0]; v[0] = k; }
            else          { v[1] = k; }
        } else { v[2] = k; }
    }
}
__device__ __forceinline__ void insk8(uint32_t k, uint32_t v[8]) {
    if (k <= v[7]) return;
    v[7] = k;
#pragma unroll
    for (int t = 7; t > 0; --t)
        if (v[t] > v[t - 1]) { uint32_t tv = v[t]; v[t] = v[t - 1]; v[t - 1] = tv; }
}
// keyed (key, code) top-8 insert for finalize
__device__ __forceinline__ void insp8(uint32_t k, int c, uint32_t v[8], int ix[8]) {
    if (k <= v[7]) return;
    v[7] = k; ix[7] = c;
#pragma unroll
    for (int t = 7; t > 0; --t) {
        if (v[t] > v[t - 1]) {
            uint32_t tv = v[t]; v[t] = v[t - 1]; v[t - 1] = tv;
            int ti = ix[t]; ix[t] = ix[t - 1]; ix[t - 1] = ti;
        }
    }
}
__device__ __forceinline__ void ins3f(float s, int c, float v[3], int ix[3]) {
    if (s > v[2]) {
        if (s > v[1]) {
            v[2] = v[1]; ix[2] = ix[1];
            if (s > v[0]) { v[1] = v[0]; ix[1] = ix[0]; v[0] = s; ix[0] = c; }
            else          { v[1] = s;    ix[1] = c; }
        } else { v[2] = s; ix[2] = c; }
    }
}

// ---------------------------------------------------------------------------
// 1) converts + column sums
// ---------------------------------------------------------------------------
__global__ void convert_x_kernel(const float* __restrict__ x) {
    const int i = (blockIdx.x * 256 + threadIdx.x) * 4;
    const float4 v = *(const float4*)(x + i);
    __nv_bfloat162* o = (__nv_bfloat162*)(g_xb + i);
    o[0] = __nv_bfloat162(__float2bfloat16_rn(v.x), __float2bfloat16_rn(v.y));
    o[1] = __nv_bfloat162(__float2bfloat16_rn(v.z), __float2bfloat16_rn(v.w));
}
__global__ void convert_cb_kernel(const float* __restrict__ cb) {
    const int b = blockIdx.x;
    const int d = threadIdx.x;
    const float* p = cb + (size_t)b * 128 * DIM + d;
    __nv_bfloat16* q = g_cbb + (size_t)b * 128 * DIM + d;
    float s = 0.0f;
#pragma unroll 8
    for (int c = 0; c < 128; ++c) {
        const float v = p[(size_t)c * DIM];
        s += v;
        q[(size_t)c * DIM] = __float2bfloat16_rn(v);
    }
    g_part_cbsum[b * DIM + d] = s;
}
__global__ void cbsum_comb_kernel() {
    const int d = threadIdx.x;
    float s = 0.0f;
#pragma unroll 8
    for (int b = 0; b < 128; ++b) s += g_part_cbsum[b * DIM + d];
    g_cbsum[d] = s;
}

// ---------------------------------------------------------------------------
// 2) multi-tile mma.sync GEMM, 2 CTAs/SM, packed-key top-3 screening
//    8 warps = 4(M) x 2(N); warp tile 32x64
// ---------------------------------------------------------------------------
__global__ void __launch_bounds__(256, 2)
gemm_topk_kernel(const __nv_bfloat16* __restrict__ xb,
                 const __nv_bfloat16* __restrict__ cbb) {
    extern __shared__ __align__(16) char smem[];
    const uint32_t sbase = smem_u32(smem);
    const uint32_t sA = sbase;
    const uint32_t sB[2] = { sbase + A_BYTES, sbase + A_BYTES + B_BYTES };

    const int tid = threadIdx.x;
    const int wid = tid >> 5, lane = tid & 31;
    const int g = lane >> 2, tig = lane & 3;
    const int wm = wid & 3, wn = wid >> 2;       // 4M x 2N

    const int row0  = blockIdx.x * MT;
    const int code0 = blockIdx.y * GROUP_CODES;

    const uint4* gx = (const uint4*)(xb + (size_t)row0 * DIM);
    const uint4* gc = (const uint4*)(cbb + (size_t)code0 * DIM);

    // ---- prologue: A + B0 ----
#pragma unroll
    for (int i = tid; i < 128 * 16; i += 256) {
        const int r = i >> 4, kc = i & 15;
        cp_async16(sA + r * STRIDE_B + kc * 16, gx + r * 16 + kc);
    }
#pragma unroll
    for (int i = tid; i < 128 * 16; i += 256) {
        const int r = i >> 4, kc = i & 15;
        cp_async16(sB[0] + r * STRIDE_B + kc * 16, gc + r * 16 + kc);
    }
    cp_commit();

    // packed top-3 keys for 4 owned rows (0 = -inf sentinel)
    uint32_t kv[4][3];
#pragma unroll
    for (int t = 0; t < 4; ++t)
#pragma unroll
        for (int s = 0; s < 3; ++s) kv[t][s] = 0u;

    // ldmatrix per-lane addressing
    const int aq = lane >> 3;
    const uint32_t fragRow = (uint32_t)((lane & 7) + (aq & 1) * 8);
    const uint32_t fragCol = (uint32_t)((aq >> 1) * 16);
    const uint32_t aOff = (uint32_t)(wm * 32) * STRIDE_B + fragRow * STRIDE_B + fragCol;
    // B ldsm: m0,m1 = rows 0-7 col0/col16B ; m2,m3 = rows 8-15 col0/col16B
    const uint32_t bFragRow = (uint32_t)((lane & 7) + (aq >> 1) * 8);
    const uint32_t bFragCol = (uint32_t)((aq & 1) * 16);
    const uint32_t bOff = (uint32_t)(wn * 64) * STRIDE_B + bFragRow * STRIDE_B + bFragCol;

#pragma unroll 1
    for (int t = 0; t < TILES_PER_GROUP; ++t) {
        __syncthreads();
        if (t + 1 < TILES_PER_GROUP) {
            const uint4* gt = gc + (size_t)(t + 1) * 128 * 16;
            const uint32_t dst = sB[(t + 1) & 1];
#pragma unroll
            for (int i = tid; i < 128 * 16; i += 256) {
                const int r = i >> 4, kc = i & 15;
                cp_async16(dst + r * STRIDE_B + kc * 16, gt + r * 16 + kc);
            }
            cp_commit();
            cp_wait1();
        } else {
            cp_wait0();
        }
        __syncthreads();

        float acc[2][8][4];
#pragma unroll
        for (int i = 0; i < 2; ++i)
#pragma unroll
            for (int j = 0; j < 8; ++j)
#pragma unroll
                for (int c = 0; c < 4; ++c) acc[i][j][c] = 0.0f;

        const uint32_t aB = sA + aOff;
        const uint32_t bB = sB[t & 1] + bOff;
#pragma unroll
        for (int ks = 0; ks < 8; ++ks) {
            const uint32_t kOff = ks * 32;
            uint32_t a[2][4];
#pragma unroll
            for (int i = 0; i < 2; ++i)
                ldsm_x4(a[i][0], a[i][1], a[i][2], a[i][3],
                        aB + (uint32_t)(16 * i) * STRIDE_B + kOff);
            uint32_t b[8][2];
#pragma unroll
            for (int jp = 0; jp < 4; ++jp)
                ldsm_x4(b[2 * jp][0], b[2 * jp][1], b[2 * jp + 1][0], b[2 * jp + 1][1],
                        bB + (uint32_t)(16 * jp) * STRIDE_B + kOff);
#pragma unroll
            for (int i = 0; i < 2; ++i)
#pragma unroll
                for (int j = 0; j < 8; ++j)
                    mma16816(acc[i][j], a[i], b[j]);
        }

        // fold tile into packed top-3 (group-local code = t*128 + col)
        const int cloc = t * NT + wn * 64 + tig * 2;
#pragma unroll
        for (int i = 0; i < 2; ++i)
#pragma unroll
            for (int j = 0; j < 8; ++j) {
                const int c0 = cloc + j * 8;
                insk3(pack_key(acc[i][j][0], c0),     kv[2 * i]);
                insk3(pack_key(acc[i][j][1], c0 + 1), kv[2 * i]);
                insk3(pack_key(acc[i][j][2], c0),     kv[2 * i + 1]);
                insk3(pack_key(acc[i][j][3], c0 + 1), kv[2 * i + 1]);
            }
    }

    // ---- CTA merge: 24 keys/row -> top-8 keys ----
    __syncthreads();
    uint32_t* skey = (uint32_t*)smem;            // [128][24] = 12288 B
#pragma unroll
    for (int s4 = 0; s4 < 4; ++s4) {
        const int r = wm * 32 + (s4 >> 1) * 16 + (s4 & 1) * 8 + g;
        const int slot = (wn * 4 + tig) * 3;
#pragma unroll
        for (int s = 0; s < 3; ++s) skey[r * 24 + slot + s] = kv[s4][s];
    }
    __syncthreads();

    if (tid < 128) {
        const int r = tid;
        uint32_t v[8];
#pragma unroll
        for (int s = 0; s < 8; ++s) v[s] = 0u;
#pragma unroll 1
        for (int q = 0; q < 24; ++q) insk8(skey[r * 24 + q], v);
        const size_t base = ((size_t)(row0 + r) * NGROUPS + blockIdx.y) * CAND;
#pragma unroll
        for (int s = 0; s < 8; ++s) g_ckey[base + s] = v[s];
    }
}

// ---------------------------------------------------------------------------
// 3) finalize: merge 128 keys, exact fp32 rescore, softmax identity
// ---------------------------------------------------------------------------
__global__ void __launch_bounds__(128)
finalize_kernel(const float* __restrict__ x, const float* __restrict__ cb,
                float* __restrict__ out) {
    const int row = blockIdx.x;
    const int tid = threadIdx.x;
    const int wid = tid >> 5, lid = tid & 31;

    __shared__ uint32_t sk[NGROUPS * CAND];      // 128 keys
    __shared__ uint32_t s2v[64];
    __shared__ int      s2i[64];
    __shared__ int      pick[8];
    __shared__ float    sex[8];
    __shared__ float    sw[4];
    __shared__ int      sid[3];

    const size_t cbase = (size_t)row * NGROUPS * CAND;
    if (tid < NGROUPS * CAND) sk[tid] = g_ckey[cbase + tid];
    __syncthreads();

    // stage 1: 8 lanes of warp 0 reduce 16 keys each -> top-8 (key, code)
    if (wid == 0 && lid < 8) {
        uint32_t v[8]; int ix[8];
#pragma unroll
        for (int s = 0; s < 8; ++s) { v[s] = 0u; ix[s] = 0; }
#pragma unroll 1
        for (int q = lid; q < NGROUPS * CAND; q += 8) {
            const uint32_t k = sk[q];
            const int code = (q >> 3) * GROUP_CODES + (int)(k & 1023u);
            insp8(k, code, v, ix);
        }
#pragma unroll
        for (int s = 0; s < 8; ++s) { s2v[lid * 8 + s] = v[s]; s2i[lid * 8 + s] = ix[s]; }
    }
    __syncthreads();

    // stage 2: single thread merges 64 -> top-8 pool
    if (tid == 0) {
        uint32_t v[8]; int ix[8];
#pragma unroll
        for (int s = 0; s < 8; ++s) { v[s] = 0u; ix[s] = 0; }
#pragma unroll 1
        for (int q = 0; q < 64; ++q) insp8(s2v[q], s2i[q], v, ix);
#pragma unroll
        for (int s = 0; s < 8; ++s) pick[s] = ix[s];
    }
    __syncthreads();

    // exact fp32 rescore: warp w handles candidates 2w, 2w+1
    const float4 xa = ((const float4*)(x + (size_t)row * DIM))[lid];
#pragma unroll
    for (int t = 0; t < 2; ++t) {
        const int cc = wid * 2 + t;
        const int c = pick[cc];
        const float4 ca = ((const float4*)(cb + (size_t)c * DIM))[lid];
        float p = xa.x * ca.x;
        p = fmaf(xa.y, ca.y, p);
        p = fmaf(xa.z, ca.z, p);
        p = fmaf(xa.w, ca.w, p);
#pragma unroll
        for (int o = 16; o > 0; o >>= 1) p += __shfl_xor_sync(0xFFFFFFFFu, p, o);
        if (lid == 0) sex[cc] = p;
    }
    __syncthreads();

    if (tid == 0) {
        float v[3] = { -3.0e38f, -3.0e38f, -3.0e38f };
        int ix[3] = { 0, 0, 0 };
#pragma unroll
        for (int q = 0; q < 8; ++q) ins3f(sex[q], pick[q], v, ix);
        const float INV_TAU = 100.0f;
        const float m  = fmaxf(v[0], 0.0f);
        const float w0 = expf((v[0] - m) * INV_TAU);
        const float w1 = expf((v[1] - m) * INV_TAU);
        const float w2 = expf((v[2] - m) * INV_TAU);
        const float b  = expf(-m * INV_TAU);
        const float Z  = w0 + w1 + w2 + b * (float)(N_CODES - TOPK);
        const float invZ = 1.0f / Z;
        sw[0] = w0 * invZ; sw[1] = w1 * invZ; sw[2] = w2 * invZ; sw[3] = b * invZ;
        sid[0] = ix[0]; sid[1] = ix[1]; sid[2] = ix[2];
    }
    __syncthreads();

    const int d = tid;
    const float c0 = cb[(size_t)sid[0] * DIM + d];
    const float c1 = cb[(size_t)sid[1] * DIM + d];
    const float c2 = cb[(size_t)sid[2] * DIM + d];
    out[(size_t)row * DIM + d] =
        sw[0] * c0 + sw[1] * c1 + sw[2] * c2 + sw[3] * (g_cbsum[d] - c0 - c1 - c2);
}

// ---------------------------------------------------------------------------
extern "C" void kernel_launch(void* const* d_in, const int* in_sizes, int n_in,
                              void* d_out, int out_size) {
    const float* x  = (const float*)d_in[0];
    const float* cb = (const float*)d_in[1];
    if (n_in >= 2 && in_sizes[0] == N_CODES * DIM && in_sizes[1] == N_ROWS * DIM) {
        x  = (const float*)d_in[1];
        cb = (const float*)d_in[0];
    }
    float* out = (float*)d_out;

    cudaFuncSetAttribute(gemm_topk_kernel,
                         cudaFuncAttributeMaxDynamicSharedMemorySize, GEMM_SMEM);

    __nv_bfloat16 *xb_p, *cbb_p;
    cudaGetSymbolAddress((void**)&xb_p, g_xb);
    cudaGetSymbolAddress((void**)&cbb_p, g_cbb);

    convert_x_kernel<<<N_ROWS * DIM / 1024, 256>>>(x);
    convert_cb_kernel<<<128, 128>>>(cb);
    cbsum_comb_kernel<<<1, 128>>>();
    gemm_topk_kernel<<<dim3(MTILES, NGROUPS), 256, GEMM_SMEM>>>(xb_p, cbb_p);
    finalize_kernel<<<N_ROWS, 128>>>(x, cb, out);
}

// round 9
// speedup vs baseline: 8.3471x; 1.2759x over previous
#include <cuda_runtime.h>
#include <cuda_bf16.h>
#include <cstdint>

// ============================================================================
// MeToken: z_q = softmax(topk3_gated(x @ cb^T) / 0.01) @ cb
//
// Identity (non-topk gated scores are 0, not -inf):
//   m = max(top1, 0), w_k = exp((s_k-m)/tau), b = exp(-m/tau)
//   Z   = w0+w1+w2 + (C-K)*b
//   z_q = (w0*cb0 + w1*cb1 + w2*cb2 + b*(colsum(cb) - cb0-cb1-cb2)) / Z
//
// R9: branchless screening fold. Top-3 keys updated with a 5-op IMNMX
// sorting chain (no predicate-guard / BSSY/BSYNC stalls). Packed u32 keys
// (monotone fp32 bits, low 10 bits = group-local code idx). Exact fp32
// rescore of the merged top-8 pool unchanged.
// ============================================================================

#define N_ROWS 8192
#define DIM 128
#define N_CODES 16384
#define TOPK 3

#define MT 128
#define NT 128                          // codes per B-subtile
#define TILES_PER_GROUP 8
#define GROUP_CODES (NT * TILES_PER_GROUP)   // 1024
#define NGROUPS (N_CODES / GROUP_CODES)      // 16
#define MTILES (N_ROWS / MT)                 // 64
#define CAND 8
#define STRIDE_B 272                    // bytes per smem row (136 bf16)
#define A_BYTES (128 * STRIDE_B)        // 34816
#define B_BYTES (128 * STRIDE_B)        // 34816
#define GEMM_SMEM (A_BYTES + 2 * B_BYTES)    // 104448

// ---------------- scratch (no allocs allowed) ----------------
__device__ __nv_bfloat16 g_xb[N_ROWS * DIM];
__device__ __nv_bfloat16 g_cbb[N_CODES * DIM];
__device__ float g_part_cbsum[128 * DIM];
__device__ float g_cbsum[DIM];
__device__ uint32_t g_ckey[(size_t)N_ROWS * NGROUPS * CAND];   // packed keys

// ---------------- helpers ----------------
__device__ __forceinline__ uint32_t smem_u32(const void* p) {
    uint32_t a;
    asm("{ .reg .u64 t; cvta.to.shared.u64 t, %1; cvt.u32.u64 %0, t; }" : "=r"(a) : "l"(p));
    return a;
}
__device__ __forceinline__ void cp_async16(uint32_t dst, const void* src) {
    asm volatile("cp.async.cg.shared.global [%0], [%1], 16;" :: "r"(dst), "l"(src) : "memory");
}
__device__ __forceinline__ void cp_commit() {
    asm volatile("cp.async.commit_group;" ::: "memory");
}
__device__ __forceinline__ void cp_wait1() {
    asm volatile("cp.async.wait_group 1;" ::: "memory");
}
__device__ __forceinline__ void cp_wait0() {
    asm volatile("cp.async.wait_group 0;" ::: "memory");
}
__device__ __forceinline__ void ldsm_x4(uint32_t& r0, uint32_t& r1, uint32_t& r2, uint32_t& r3,
                                        uint32_t addr) {
    asm volatile("ldmatrix.sync.aligned.m8n8.x4.shared.b16 {%0,%1,%2,%3}, [%4];"
                 : "=r"(r0), "=r"(r1), "=r"(r2), "=r"(r3) : "r"(addr));
}
__device__ __forceinline__ void mma16816(float c[4], const uint32_t a[4], const uint32_t b[2]) {
    asm volatile(
        "mma.sync.aligned.m16n8k16.row.col.f32.bf16.bf16.f32 "
        "{%0,%1,%2,%3}, {%4,%5,%6,%7}, {%8,%9}, {%0,%1,%2,%3};"
        : "+f"(c[0]), "+f"(c[1]), "+f"(c[2]), "+f"(c[3])
        : "r"(a[0]), "r"(a[1]), "r"(a[2]), "r"(a[3]), "r"(b[0]), "r"(b[1]));
}

// monotone fp32 -> u32 key; low 10 bits carry group-local code index
__device__ __forceinline__ uint32_t pack_key(float s, int lidx) {
    uint32_t u = __float_as_uint(s);
    u ^= (uint32_t)((int32_t)u >> 31) | 0x80000000u;
    return (u & 0xFFFFFC00u) | (uint32_t)lidx;
}
// branchless top-3 fold: 5 IMNMX, no branches
__device__ __forceinline__ void fold3(uint32_t k, uint32_t v[3]) {
    const uint32_t t0 = max(v[0], k);
    const uint32_t m0 = min(v[0], k);
    const uint32_t t1 = max(v[1], m0);
    const uint32_t m1 = min(v[1], m0);
    const uint32_t t2 = max(v[2], m1);
    v[0] = t0; v[1] = t1; v[2] = t2;
}
__device__ __forceinline__ void insk8(uint32_t k, uint32_t v[8]) {
    if (k <= v[7]) return;
    v[7] = k;
#pragma unroll
    for (int t = 7; t > 0; --t)
        if (v[t] > v[t - 1]) { uint32_t tv = v[t]; v[t] = v[t - 1]; v[t - 1] = tv; }
}
// keyed (key, code) top-8 insert for finalize
__device__ __forceinline__ void insp8(uint32_t k, int c, uint32_t v[8], int ix[8]) {
    if (k <= v[7]) return;
    v[7] = k; ix[7] = c;
#pragma unroll
    for (int t = 7; t > 0; --t) {
        if (v[t] > v[t - 1]) {
            uint32_t tv = v[t]; v[t] = v[t - 1]; v[t - 1] = tv;
            int ti = ix[t]; ix[t] = ix[t - 1]; ix[t - 1] = ti;
        }
    }
}
__device__ __forceinline__ void ins3f(float s, int c, float v[3], int ix[3]) {
    if (s > v[2]) {
        if (s > v[1]) {
            v[2] = v[1]; ix[2] = ix[1];
            if (s > v[0]) { v[1] = v[0]; ix[1] = ix[0]; v[0] = s; ix[0] = c; }
            else          { v[1] = s;    ix[1] = c; }
        } else { v[2] = s; ix[2] = c; }
    }
}

// ---------------------------------------------------------------------------
// 1) converts + column sums
// ---------------------------------------------------------------------------
__global__ void convert_x_kernel(const float* __restrict__ x) {
    const int i = (blockIdx.x * 256 + threadIdx.x) * 4;
    const float4 v = *(const float4*)(x + i);
    __nv_bfloat162* o = (__nv_bfloat162*)(g_xb + i);
    o[0] = __nv_bfloat162(__float2bfloat16_rn(v.x), __float2bfloat16_rn(v.y));
    o[1] = __nv_bfloat162(__float2bfloat16_rn(v.z), __float2bfloat16_rn(v.w));
}
__global__ void convert_cb_kernel(const float* __restrict__ cb) {
    const int b = blockIdx.x;
    const int d = threadIdx.x;
    const float* p = cb + (size_t)b * 128 * DIM + d;
    __nv_bfloat16* q = g_cbb + (size_t)b * 128 * DIM + d;
    float s = 0.0f;
#pragma unroll 8
    for (int c = 0; c < 128; ++c) {
        const float v = p[(size_t)c * DIM];
        s += v;
        q[(size_t)c * DIM] = __float2bfloat16_rn(v);
    }
    g_part_cbsum[b * DIM + d] = s;
}
__global__ void cbsum_comb_kernel() {
    const int d = threadIdx.x;
    float s = 0.0f;
#pragma unroll 8
    for (int b = 0; b < 128; ++b) s += g_part_cbsum[b * DIM + d];
    g_cbsum[d] = s;
}

// ---------------------------------------------------------------------------
// 2) multi-tile mma.sync GEMM, 2 CTAs/SM, branchless packed-key screening
//    8 warps = 4(M) x 2(N); warp tile 32x64
// ---------------------------------------------------------------------------
__global__ void __launch_bounds__(256, 2)
gemm_topk_kernel(const __nv_bfloat16* __restrict__ xb,
                 const __nv_bfloat16* __restrict__ cbb) {
    extern __shared__ __align__(16) char smem[];
    const uint32_t sbase = smem_u32(smem);
    const uint32_t sA = sbase;
    const uint32_t sB[2] = { sbase + A_BYTES, sbase + A_BYTES + B_BYTES };

    const int tid = threadIdx.x;
    const int wid = tid >> 5, lane = tid & 31;
    const int g = lane >> 2, tig = lane & 3;
    const int wm = wid & 3, wn = wid >> 2;       // 4M x 2N

    const int row0  = blockIdx.x * MT;
    const int code0 = blockIdx.y * GROUP_CODES;

    const uint4* gx = (const uint4*)(xb + (size_t)row0 * DIM);
    const uint4* gc = (const uint4*)(cbb + (size_t)code0 * DIM);

    // ---- prologue: A + B0 ----
#pragma unroll
    for (int i = tid; i < 128 * 16; i += 256) {
        const int r = i >> 4, kc = i & 15;
        cp_async16(sA + r * STRIDE_B + kc * 16, gx + r * 16 + kc);
    }
#pragma unroll
    for (int i = tid; i < 128 * 16; i += 256) {
        const int r = i >> 4, kc = i & 15;
        cp_async16(sB[0] + r * STRIDE_B + kc * 16, gc + r * 16 + kc);
    }
    cp_commit();

    // packed top-3 keys for 4 owned rows (0 = -inf sentinel)
    uint32_t kv[4][3];
#pragma unroll
    for (int t = 0; t < 4; ++t)
#pragma unroll
        for (int s = 0; s < 3; ++s) kv[t][s] = 0u;

    // ldmatrix per-lane addressing
    const int aq = lane >> 3;
    const uint32_t fragRow = (uint32_t)((lane & 7) + (aq & 1) * 8);
    const uint32_t fragCol = (uint32_t)((aq >> 1) * 16);
    const uint32_t aOff = (uint32_t)(wm * 32) * STRIDE_B + fragRow * STRIDE_B + fragCol;
    const uint32_t bFragRow = (uint32_t)((lane & 7) + (aq >> 1) * 8);
    const uint32_t bFragCol = (uint32_t)((aq & 1) * 16);
    const uint32_t bOff = (uint32_t)(wn * 64) * STRIDE_B + bFragRow * STRIDE_B + bFragCol;

#pragma unroll 1
    for (int t = 0; t < TILES_PER_GROUP; ++t) {
        __syncthreads();
        if (t + 1 < TILES_PER_GROUP) {
            const uint4* gt = gc + (size_t)(t + 1) * 128 * 16;
            const uint32_t dst = sB[(t + 1) & 1];
#pragma unroll
            for (int i = tid; i < 128 * 16; i += 256) {
                const int r = i >> 4, kc = i & 15;
                cp_async16(dst + r * STRIDE_B + kc * 16, gt + r * 16 + kc);
            }
            cp_commit();
            cp_wait1();
        } else {
            cp_wait0();
        }
        __syncthreads();

        float acc[2][8][4];
#pragma unroll
        for (int i = 0; i < 2; ++i)
#pragma unroll
            for (int j = 0; j < 8; ++j)
#pragma unroll
                for (int c = 0; c < 4; ++c) acc[i][j][c] = 0.0f;

        const uint32_t aB = sA + aOff;
        const uint32_t bB = sB[t & 1] + bOff;
#pragma unroll
        for (int ks = 0; ks < 8; ++ks) {
            const uint32_t kOff = ks * 32;
            uint32_t a[2][4];
#pragma unroll
            for (int i = 0; i < 2; ++i)
                ldsm_x4(a[i][0], a[i][1], a[i][2], a[i][3],
                        aB + (uint32_t)(16 * i) * STRIDE_B + kOff);
            uint32_t b[8][2];
#pragma unroll
            for (int jp = 0; jp < 4; ++jp)
                ldsm_x4(b[2 * jp][0], b[2 * jp][1], b[2 * jp + 1][0], b[2 * jp + 1][1],
                        bB + (uint32_t)(16 * jp) * STRIDE_B + kOff);
#pragma unroll
            for (int i = 0; i < 2; ++i)
#pragma unroll
                for (int j = 0; j < 8; ++j)
                    mma16816(acc[i][j], a[i], b[j]);
        }

        // fold tile into packed top-3 (branchless IMNMX chains)
        const int cloc = t * NT + wn * 64 + tig * 2;
#pragma unroll
        for (int i = 0; i < 2; ++i)
#pragma unroll
            for (int j = 0; j < 8; ++j) {
                const int c0 = cloc + j * 8;
                fold3(pack_key(acc[i][j][0], c0),     kv[2 * i]);
                fold3(pack_key(acc[i][j][1], c0 + 1), kv[2 * i]);
                fold3(pack_key(acc[i][j][2], c0),     kv[2 * i + 1]);
                fold3(pack_key(acc[i][j][3], c0 + 1), kv[2 * i + 1]);
            }
    }

    // ---- CTA merge: 24 keys/row -> top-8 keys ----
    __syncthreads();
    uint32_t* skey = (uint32_t*)smem;            // [128][24] = 12288 B
#pragma unroll
    for (int s4 = 0; s4 < 4; ++s4) {
        const int r = wm * 32 + (s4 >> 1) * 16 + (s4 & 1) * 8 + g;
        const int slot = (wn * 4 + tig) * 3;
#pragma unroll
        for (int s = 0; s < 3; ++s) skey[r * 24 + slot + s] = kv[s4][s];
    }
    __syncthreads();

    if (tid < 128) {
        const int r = tid;
        uint32_t v[8];
#pragma unroll
        for (int s = 0; s < 8; ++s) v[s] = 0u;
#pragma unroll 1
        for (int q = 0; q < 24; ++q) insk8(skey[r * 24 + q], v);
        const size_t base = ((size_t)(row0 + r) * NGROUPS + blockIdx.y) * CAND;
#pragma unroll
        for (int s = 0; s < 8; ++s) g_ckey[base + s] = v[s];
    }
}

// ---------------------------------------------------------------------------
// 3) finalize: merge 128 keys, exact fp32 rescore, softmax identity
// ---------------------------------------------------------------------------
__global__ void __launch_bounds__(128)
finalize_kernel(const float* __restrict__ x, const float* __restrict__ cb,
                float* __restrict__ out) {
    const int row = blockIdx.x;
    const int tid = threadIdx.x;
    const int wid = tid >> 5, lid = tid & 31;

    __shared__ uint32_t sk[NGROUPS * CAND];      // 128 keys
    __shared__ uint32_t s2v[64];
    __shared__ int      s2i[64];
    __shared__ int      pick[8];
    __shared__ float    sex[8];
    __shared__ float    sw[4];
    __shared__ int      sid[3];

    const size_t cbase = (size_t)row * NGROUPS * CAND;
    if (tid < NGROUPS * CAND) sk[tid] = g_ckey[cbase + tid];
    __syncthreads();

    // stage 1: 8 lanes of warp 0 reduce 16 keys each -> top-8 (key, code)
    if (wid == 0 && lid < 8) {
        uint32_t v[8]; int ix[8];
#pragma unroll
        for (int s = 0; s < 8; ++s) { v[s] = 0u; ix[s] = 0; }
#pragma unroll 1
        for (int q = lid; q < NGROUPS * CAND; q += 8) {
            const uint32_t k = sk[q];
            const int code = (q >> 3) * GROUP_CODES + (int)(k & 1023u);
            insp8(k, code, v, ix);
        }
#pragma unroll
        for (int s = 0; s < 8; ++s) { s2v[lid * 8 + s] = v[s]; s2i[lid * 8 + s] = ix[s]; }
    }
    __syncthreads();

    // stage 2: single thread merges 64 -> top-8 pool
    if (tid == 0) {
        uint32_t v[8]; int ix[8];
#pragma unroll
        for (int s = 0; s < 8; ++s) { v[s] = 0u; ix[s] = 0; }
#pragma unroll 1
        for (int q = 0; q < 64; ++q) insp8(s2v[q], s2i[q], v, ix);
#pragma unroll
        for (int s = 0; s < 8; ++s) pick[s] = ix[s];
    }
    __syncthreads();

    // exact fp32 rescore: warp w handles candidates 2w, 2w+1
    const float4 xa = ((const float4*)(x + (size_t)row * DIM))[lid];
#pragma unroll
    for (int t = 0; t < 2; ++t) {
        const int cc = wid * 2 + t;
        const int c = pick[cc];
        const float4 ca = ((const float4*)(cb + (size_t)c * DIM))[lid];
        float p = xa.x * ca.x;
        p = fmaf(xa.y, ca.y, p);
        p = fmaf(xa.z, ca.z, p);
        p = fmaf(xa.w, ca.w, p);
#pragma unroll
        for (int o = 16; o > 0; o >>= 1) p += __shfl_xor_sync(0xFFFFFFFFu, p, o);
        if (lid == 0) sex[cc] = p;
    }
    __syncthreads();

    if (tid == 0) {
        float v[3] = { -3.0e38f, -3.0e38f, -3.0e38f };
        int ix[3] = { 0, 0, 0 };
#pragma unroll
        for (int q = 0; q < 8; ++q) ins3f(sex[q], pick[q], v, ix);
        const float INV_TAU = 100.0f;
        const float m  = fmaxf(v[0], 0.0f);
        const float w0 = expf((v[0] - m) * INV_TAU);
        const float w1 = expf((v[1] - m) * INV_TAU);
        const float w2 = expf((v[2] - m) * INV_TAU);
        const float b  = expf(-m * INV_TAU);
        const float Z  = w0 + w1 + w2 + b * (float)(N_CODES - TOPK);
        const float invZ = 1.0f / Z;
        sw[0] = w0 * invZ; sw[1] = w1 * invZ; sw[2] = w2 * invZ; sw[3] = b * invZ;
        sid[0] = ix[0]; sid[1] = ix[1]; sid[2] = ix[2];
    }
    __syncthreads();

    const int d = tid;
    const float c0 = cb[(size_t)sid[0] * DIM + d];
    const float c1 = cb[(size_t)sid[1] * DIM + d];
    const float c2 = cb[(size_t)sid[2] * DIM + d];
    out[(size_t)row * DIM + d] =
        sw[0] * c0 + sw[1] * c1 + sw[2] * c2 + sw[3] * (g_cbsum[d] - c0 - c1 - c2);
}

// ---------------------------------------------------------------------------
extern "C" void kernel_launch(void* const* d_in, const int* in_sizes, int n_in,
                              void* d_out, int out_size) {
    const float* x  = (const float*)d_in[0];
    const float* cb = (const float*)d_in[1];
    if (n_in >= 2 && in_sizes[0] == N_CODES * DIM && in_sizes[1] == N_ROWS * DIM) {
        x  = (const float*)d_in[1];
        cb = (const float*)d_in[0];
    }
    float* out = (float*)d_out;

    cudaFuncSetAttribute(gemm_topk_kernel,
                         cudaFuncAttributeMaxDynamicSharedMemorySize, GEMM_SMEM);

    __nv_bfloat16 *xb_p, *cbb_p;
    cudaGetSymbolAddress((void**)&xb_p, g_xb);
    cudaGetSymbolAddress((void**)&cbb_p, g_cbb);

    convert_x_kernel<<<N_ROWS * DIM / 1024, 256>>>(x);
    convert_cb_kernel<<<128, 128>>>(cb);
    cbsum_comb_kernel<<<1, 128>>>();
    gemm_topk_kernel<<<dim3(MTILES, NGROUPS), 256, GEMM_SMEM>>>(xb_p, cbb_p);
    finalize_kernel<<<N_ROWS, 128>>>(x, cb, out);
}

// round 10
// speedup vs baseline: 8.5754x; 1.0273x over previous
#include <cuda_runtime.h>
#include <cuda_bf16.h>
#include <cstdint>

// ============================================================================
// MeToken: z_q = softmax(topk3_gated(x @ cb^T) / 0.01) @ cb
//
// Identity (non-topk gated scores are 0, not -inf):
//   m = max(top1, 0), w_k = exp((s_k-m)/tau), b = exp(-m/tau)
//   Z   = w0+w1+w2 + (C-K)*b
//   z_q = (w0*cb0 + w1*cb1 + w2*cb2 + b*(colsum(cb) - cb0-cb1-cb2)) / Z
//
// R10: float-domain screening keys. Index lives in the low 10 mantissa bits
// (single LOP3 pack); top-3 fold is a 5-op fmaxf/fminf chain. Cuts screening
// ALU ops ~1.5x vs R9. Exact fp32 rescore of merged top-8 pool unchanged.
// ============================================================================

#define N_ROWS 8192
#define DIM 128
#define N_CODES 16384
#define TOPK 3

#define MT 128
#define NT 128                          // codes per B-subtile
#define TILES_PER_GROUP 8
#define GROUP_CODES (NT * TILES_PER_GROUP)   // 1024
#define NGROUPS (N_CODES / GROUP_CODES)      // 16
#define MTILES (N_ROWS / MT)                 // 64
#define CAND 8
#define STRIDE_B 272                    // bytes per smem row (136 bf16)
#define A_BYTES (128 * STRIDE_B)        // 34816
#define B_BYTES (128 * STRIDE_B)        // 34816
#define GEMM_SMEM (A_BYTES + 2 * B_BYTES)    // 104448

#define NEG_SENT (-3.0e38f)

// ---------------- scratch (no allocs allowed) ----------------
__device__ __nv_bfloat16 g_xb[N_ROWS * DIM];
__device__ __nv_bfloat16 g_cbb[N_CODES * DIM];
__device__ float g_part_cbsum[128 * DIM];
__device__ float g_cbsum[DIM];
__device__ float g_ckey[(size_t)N_ROWS * NGROUPS * CAND];   // float keys (idx in low bits)

// ---------------- helpers ----------------
__device__ __forceinline__ uint32_t smem_u32(const void* p) {
    uint32_t a;
    asm("{ .reg .u64 t; cvta.to.shared.u64 t, %1; cvt.u32.u64 %0, t; }" : "=r"(a) : "l"(p));
    return a;
}
__device__ __forceinline__ void cp_async16(uint32_t dst, const void* src) {
    asm volatile("cp.async.cg.shared.global [%0], [%1], 16;" :: "r"(dst), "l"(src) : "memory");
}
__device__ __forceinline__ void cp_commit() {
    asm volatile("cp.async.commit_group;" ::: "memory");
}
__device__ __forceinline__ void cp_wait1() {
    asm volatile("cp.async.wait_group 1;" ::: "memory");
}
__device__ __forceinline__ void cp_wait0() {
    asm volatile("cp.async.wait_group 0;" ::: "memory");
}
__device__ __forceinline__ void ldsm_x4(uint32_t& r0, uint32_t& r1, uint32_t& r2, uint32_t& r3,
                                        uint32_t addr) {
    asm volatile("ldmatrix.sync.aligned.m8n8.x4.shared.b16 {%0,%1,%2,%3}, [%4];"
                 : "=r"(r0), "=r"(r1), "=r"(r2), "=r"(r3) : "r"(addr));
}
__device__ __forceinline__ void mma16816(float c[4], const uint32_t a[4], const uint32_t b[2]) {
    asm volatile(
        "mma.sync.aligned.m16n8k16.row.col.f32.bf16.bf16.f32 "
        "{%0,%1,%2,%3}, {%4,%5,%6,%7}, {%8,%9}, {%0,%1,%2,%3};"
        : "+f"(c[0]), "+f"(c[1]), "+f"(c[2]), "+f"(c[3])
        : "r"(a[0]), "r"(a[1]), "r"(a[2]), "r"(a[3]), "r"(b[0]), "r"(b[1]));
}

// float key: low 10 mantissa bits replaced by group-local code index (1 LOP3)
__device__ __forceinline__ float pack_keyf(float s, int lidx) {
    return __uint_as_float((__float_as_uint(s) & 0xFFFFFC00u) | (uint32_t)lidx);
}
// branchless top-3 fold: 5 FMNMX, no branches
__device__ __forceinline__ void fold3f(float k, float v[3]) {
    const float t0 = fmaxf(v[0], k);
    const float m0 = fminf(v[0], k);
    const float t1 = fmaxf(v[1], m0);
    const float m1 = fminf(v[1], m0);
    const float t2 = fmaxf(v[2], m1);
    v[0] = t0; v[1] = t1; v[2] = t2;
}
__device__ __forceinline__ void insk8f(float k, float v[8]) {
    if (k <= v[7]) return;
    v[7] = k;
#pragma unroll
    for (int t = 7; t > 0; --t)
        if (v[t] > v[t - 1]) { float tv = v[t]; v[t] = v[t - 1]; v[t - 1] = tv; }
}
// keyed (float key, code) top-8 insert for finalize
__device__ __forceinline__ void insp8f(float k, int c, float v[8], int ix[8]) {
    if (k <= v[7]) return;
    v[7] = k; ix[7] = c;
#pragma unroll
    for (int t = 7; t > 0; --t) {
        if (v[t] > v[t - 1]) {
            float tv = v[t]; v[t] = v[t - 1]; v[t - 1] = tv;
            int ti = ix[t]; ix[t] = ix[t - 1]; ix[t - 1] = ti;
        }
    }
}
__device__ __forceinline__ void ins3f(float s, int c, float v[3], int ix[3]) {
    if (s > v[2]) {
        if (s > v[1]) {
            v[2] = v[1]; ix[2] = ix[1];
            if (s > v[0]) { v[1] = v[0]; ix[1] = ix[0]; v[0] = s; ix[0] = c; }
            else          { v[1] = s;    ix[1] = c; }
        } else { v[2] = s; ix[2] = c; }
    }
}

// ---------------------------------------------------------------------------
// 1) converts + column sums
// ---------------------------------------------------------------------------
__global__ void convert_x_kernel(const float* __restrict__ x) {
    const int i = (blockIdx.x * 256 + threadIdx.x) * 4;
    const float4 v = *(const float4*)(x + i);
    __nv_bfloat162* o = (__nv_bfloat162*)(g_xb + i);
    o[0] = __nv_bfloat162(__float2bfloat16_rn(v.x), __float2bfloat16_rn(v.y));
    o[1] = __nv_bfloat162(__float2bfloat16_rn(v.z), __float2bfloat16_rn(v.w));
}
__global__ void convert_cb_kernel(const float* __restrict__ cb) {
    const int b = blockIdx.x;
    const int d = threadIdx.x;
    const float* p = cb + (size_t)b * 128 * DIM + d;
    __nv_bfloat16* q = g_cbb + (size_t)b * 128 * DIM + d;
    float s = 0.0f;
#pragma unroll 8
    for (int c = 0; c < 128; ++c) {
        const float v = p[(size_t)c * DIM];
        s += v;
        q[(size_t)c * DIM] = __float2bfloat16_rn(v);
    }
    g_part_cbsum[b * DIM + d] = s;
}
__global__ void cbsum_comb_kernel() {
    const int d = threadIdx.x;
    float s = 0.0f;
#pragma unroll 8
    for (int b = 0; b < 128; ++b) s += g_part_cbsum[b * DIM + d];
    g_cbsum[d] = s;
}

// ---------------------------------------------------------------------------
// 2) multi-tile mma.sync GEMM, 2 CTAs/SM, float-key branchless screening
//    8 warps = 4(M) x 2(N); warp tile 32x64
// ---------------------------------------------------------------------------
__global__ void __launch_bounds__(256, 2)
gemm_topk_kernel(const __nv_bfloat16* __restrict__ xb,
                 const __nv_bfloat16* __restrict__ cbb) {
    extern __shared__ __align__(16) char smem[];
    const uint32_t sbase = smem_u32(smem);
    const uint32_t sA = sbase;
    const uint32_t sB[2] = { sbase + A_BYTES, sbase + A_BYTES + B_BYTES };

    const int tid = threadIdx.x;
    const int wid = tid >> 5, lane = tid & 31;
    const int g = lane >> 2, tig = lane & 3;
    const int wm = wid & 3, wn = wid >> 2;       // 4M x 2N

    const int row0  = blockIdx.x * MT;
    const int code0 = blockIdx.y * GROUP_CODES;

    const uint4* gx = (const uint4*)(xb + (size_t)row0 * DIM);
    const uint4* gc = (const uint4*)(cbb + (size_t)code0 * DIM);

    // ---- prologue: A + B0 ----
#pragma unroll
    for (int i = tid; i < 128 * 16; i += 256) {
        const int r = i >> 4, kc = i & 15;
        cp_async16(sA + r * STRIDE_B + kc * 16, gx + r * 16 + kc);
    }
#pragma unroll
    for (int i = tid; i < 128 * 16; i += 256) {
        const int r = i >> 4, kc = i & 15;
        cp_async16(sB[0] + r * STRIDE_B + kc * 16, gc + r * 16 + kc);
    }
    cp_commit();

    // float top-3 keys for 4 owned rows
    float kv[4][3];
#pragma unroll
    for (int t = 0; t < 4; ++t)
#pragma unroll
        for (int s = 0; s < 3; ++s) kv[t][s] = NEG_SENT;

    // ldmatrix per-lane addressing
    const int aq = lane >> 3;
    const uint32_t fragRow = (uint32_t)((lane & 7) + (aq & 1) * 8);
    const uint32_t fragCol = (uint32_t)((aq >> 1) * 16);
    const uint32_t aOff = (uint32_t)(wm * 32) * STRIDE_B + fragRow * STRIDE_B + fragCol;
    const uint32_t bFragRow = (uint32_t)((lane & 7) + (aq >> 1) * 8);
    const uint32_t bFragCol = (uint32_t)((aq & 1) * 16);
    const uint32_t bOff = (uint32_t)(wn * 64) * STRIDE_B + bFragRow * STRIDE_B + bFragCol;

#pragma unroll 1
    for (int t = 0; t < TILES_PER_GROUP; ++t) {
        __syncthreads();
        if (t + 1 < TILES_PER_GROUP) {
            const uint4* gt = gc + (size_t)(t + 1) * 128 * 16;
            const uint32_t dst = sB[(t + 1) & 1];
#pragma unroll
            for (int i = tid; i < 128 * 16; i += 256) {
                const int r = i >> 4, kc = i & 15;
                cp_async16(dst + r * STRIDE_B + kc * 16, gt + r * 16 + kc);
            }
            cp_commit();
            cp_wait1();
        } else {
            cp_wait0();
        }
        __syncthreads();

        float acc[2][8][4];
#pragma unroll
        for (int i = 0; i < 2; ++i)
#pragma unroll
            for (int j = 0; j < 8; ++j)
#pragma unroll
                for (int c = 0; c < 4; ++c) acc[i][j][c] = 0.0f;

        const uint32_t aB = sA + aOff;
        const uint32_t bB = sB[t & 1] + bOff;
#pragma unroll
        for (int ks = 0; ks < 8; ++ks) {
            const uint32_t kOff = ks * 32;
            uint32_t a[2][4];
#pragma unroll
            for (int i = 0; i < 2; ++i)
                ldsm_x4(a[i][0], a[i][1], a[i][2], a[i][3],
                        aB + (uint32_t)(16 * i) * STRIDE_B + kOff);
            uint32_t b[8][2];
#pragma unroll
            for (int jp = 0; jp < 4; ++jp)
                ldsm_x4(b[2 * jp][0], b[2 * jp][1], b[2 * jp + 1][0], b[2 * jp + 1][1],
                        bB + (uint32_t)(16 * jp) * STRIDE_B + kOff);
#pragma unroll
            for (int i = 0; i < 2; ++i)
#pragma unroll
                for (int j = 0; j < 8; ++j)
                    mma16816(acc[i][j], a[i], b[j]);
        }

        // fold tile into float top-3 (1 LOP3 pack + 5 FMNMX per score)
        const int cloc = t * NT + wn * 64 + tig * 2;
#pragma unroll
        for (int i = 0; i < 2; ++i)
#pragma unroll
            for (int j = 0; j < 8; ++j) {
                const int c0 = cloc + j * 8;
                fold3f(pack_keyf(acc[i][j][0], c0),     kv[2 * i]);
                fold3f(pack_keyf(acc[i][j][1], c0 + 1), kv[2 * i]);
                fold3f(pack_keyf(acc[i][j][2], c0),     kv[2 * i + 1]);
                fold3f(pack_keyf(acc[i][j][3], c0 + 1), kv[2 * i + 1]);
            }
    }

    // ---- CTA merge: 24 keys/row -> top-8 keys ----
    __syncthreads();
    float* skey = (float*)smem;                  // [128][24] = 12288 B
#pragma unroll
    for (int s4 = 0; s4 < 4; ++s4) {
        const int r = wm * 32 + (s4 >> 1) * 16 + (s4 & 1) * 8 + g;
        const int slot = (wn * 4 + tig) * 3;
#pragma unroll
        for (int s = 0; s < 3; ++s) skey[r * 24 + slot + s] = kv[s4][s];
    }
    __syncthreads();

    if (tid < 128) {
        const int r = tid;
        float v[8];
#pragma unroll
        for (int s = 0; s < 8; ++s) v[s] = NEG_SENT;
#pragma unroll 1
        for (int q = 0; q < 24; ++q) insk8f(skey[r * 24 + q], v);
        const size_t base = ((size_t)(row0 + r) * NGROUPS + blockIdx.y) * CAND;
#pragma unroll
        for (int s = 0; s < 8; ++s) g_ckey[base + s] = v[s];
    }
}

// ---------------------------------------------------------------------------
// 3) finalize: merge 128 keys, exact fp32 rescore, softmax identity
// ---------------------------------------------------------------------------
__global__ void __launch_bounds__(128)
finalize_kernel(const float* __restrict__ x, const float* __restrict__ cb,
                float* __restrict__ out) {
    const int row = blockIdx.x;
    const int tid = threadIdx.x;
    const int wid = tid >> 5, lid = tid & 31;

    __shared__ float sk[NGROUPS * CAND];         // 128 keys
    __shared__ float s2v[64];
    __shared__ int   s2i[64];
    __shared__ int   pick[8];
    __shared__ float sex[8];
    __shared__ float sw[4];
    __shared__ int   sid[3];

    const size_t cbase = (size_t)row * NGROUPS * CAND;
    if (tid < NGROUPS * CAND) sk[tid] = g_ckey[cbase + tid];
    __syncthreads();

    // stage 1: 8 lanes of warp 0 reduce 16 keys each -> top-8 (key, code)
    if (wid == 0 && lid < 8) {
        float v[8]; int ix[8];
#pragma unroll
        for (int s = 0; s < 8; ++s) { v[s] = NEG_SENT; ix[s] = 0; }
#pragma unroll 1
        for (int q = lid; q < NGROUPS * CAND; q += 8) {
            const float k = sk[q];
            const int code = (q >> 3) * GROUP_CODES + (int)(__float_as_uint(k) & 1023u);
            insp8f(k, code, v, ix);
        }
#pragma unroll
        for (int s = 0; s < 8; ++s) { s2v[lid * 8 + s] = v[s]; s2i[lid * 8 + s] = ix[s]; }
    }
    __syncthreads();

    // stage 2: single thread merges 64 -> top-8 pool
    if (tid == 0) {
        float v[8]; int ix[8];
#pragma unroll
        for (int s = 0; s < 8; ++s) { v[s] = NEG_SENT; ix[s] = 0; }
#pragma unroll 1
        for (int q = 0; q < 64; ++q) insp8f(s2v[q], s2i[q], v, ix);
#pragma unroll
        for (int s = 0; s < 8; ++s) pick[s] = ix[s];
    }
    __syncthreads();

    // exact fp32 rescore: warp w handles candidates 2w, 2w+1
    const float4 xa = ((const float4*)(x + (size_t)row * DIM))[lid];
#pragma unroll
    for (int t = 0; t < 2; ++t) {
        const int cc = wid * 2 + t;
        const int c = pick[cc];
        const float4 ca = ((const float4*)(cb + (size_t)c * DIM))[lid];
        float p = xa.x * ca.x;
        p = fmaf(xa.y, ca.y, p);
        p = fmaf(xa.z, ca.z, p);
        p = fmaf(xa.w, ca.w, p);
#pragma unroll
        for (int o = 16; o > 0; o >>= 1) p += __shfl_xor_sync(0xFFFFFFFFu, p, o);
        if (lid == 0) sex[cc] = p;
    }
    __syncthreads();

    if (tid == 0) {
        float v[3] = { NEG_SENT, NEG_SENT, NEG_SENT };
        int ix[3] = { 0, 0, 0 };
#pragma unroll
        for (int q = 0; q < 8; ++q) ins3f(sex[q], pick[q], v, ix);
        const float INV_TAU = 100.0f;
        const float m  = fmaxf(v[0], 0.0f);
        const float w0 = expf((v[0] - m) * INV_TAU);
        const float w1 = expf((v[1] - m) * INV_TAU);
        const float w2 = expf((v[2] - m) * INV_TAU);
        const float b  = expf(-m * INV_TAU);
        const float Z  = w0 + w1 + w2 + b * (float)(N_CODES - TOPK);
        const float invZ = 1.0f / Z;
        sw[0] = w0 * invZ; sw[1] = w1 * invZ; sw[2] = w2 * invZ; sw[3] = b * invZ;
        sid[0] = ix[0]; sid[1] = ix[1]; sid[2] = ix[2];
    }
    __syncthreads();

    const int d = tid;
    const float c0 = cb[(size_t)sid[0] * DIM + d];
    const float c1 = cb[(size_t)sid[1] * DIM + d];
    const float c2 = cb[(size_t)sid[2] * DIM + d];
    out[(size_t)row * DIM + d] =
        sw[0] * c0 + sw[1] * c1 + sw[2] * c2 + sw[3] * (g_cbsum[d] - c0 - c1 - c2);
}

// ---------------------------------------------------------------------------
extern "C" void kernel_launch(void* const* d_in, const int* in_sizes, int n_in,
                              void* d_out, int out_size) {
    const float* x  = (const float*)d_in[0];
    const float* cb = (const float*)d_in[1];
    if (n_in >= 2 && in_sizes[0] == N_CODES * DIM && in_sizes[1] == N_ROWS * DIM) {
        x  = (const float*)d_in[1];
        cb = (const float*)d_in[0];
    }
    float* out = (float*)d_out;

    cudaFuncSetAttribute(gemm_topk_kernel,
                         cudaFuncAttributeMaxDynamicSharedMemorySize, GEMM_SMEM);

    __nv_bfloat16 *xb_p, *cbb_p;
    cudaGetSymbolAddress((void**)&xb_p, g_xb);
    cudaGetSymbolAddress((void**)&cbb_p, g_cbb);

    convert_x_kernel<<<N_ROWS * DIM / 1024, 256>>>(x);
    convert_cb_kernel<<<128, 128>>>(cb);
    cbsum_comb_kernel<<<1, 128>>>();
    gemm_topk_kernel<<<dim3(MTILES, NGROUPS), 256, GEMM_SMEM>>>(xb_p, cbb_p);
    finalize_kernel<<<N_ROWS, 128>>>(x, cb, out);
}